// round 6
// baseline (speedup 1.0000x reference)
#include <cuda_runtime.h>
#include <cuda_fp16.h>
#include <cstdint>
#include <math.h>

#define NN 100000
#define DD 64
#define EE 1600000
#define EPSF 1e-8f
#define CAP 64   // fixed CSR capacity per node (deg ~ Poisson(16); P(>64)~1e-19)

// Scratch (static device globals — no allocation)
__device__ __align__(16) __half g_h0h[NN * DD];   // h0 in fp16 (gather table)
__device__ int g_cur[NN];                         // slot cursor == degree
__device__ int g_csr[NN * CAP];
// [0]=cr_init, [1]=scale_m, [2]=scale_fin, [3]=cr0
__device__ float g_scalars[4];
__device__ int g_flag;                            // scale_fin published

// ---- packed f32x2 helpers (FFMA2) ----
#define FMA_F32X2(d, a, b, c) \
    asm("fma.rn.f32x2 %0, %1, %2, %3;" : "=l"(d) : "l"(a), "l"(b), "l"(c))
#define PACK_F32X2(out, lo, hi) \
    asm("mov.b64 %0, {%1, %2};" : "=l"(out) : "r"(lo), "r"(hi))
#define UNPACK_F32X2(lo, hi, in) \
    asm("mov.b64 {%0, %1}, %2;" : "=r"(lo), "=r"(hi) : "l"(in))

__device__ __forceinline__ float warp_reduce_add(float v) {
#pragma unroll
    for (int o = 16; o; o >>= 1) v += __shfl_xor_sync(0xffffffffu, v, o);
    return v;
}

__device__ __forceinline__ float compute_scale(float cr_cur, float cr_ref) {
    float ratio = cr_ref / (cr_cur + EPSF);
    bool cond = (!isnan(cr_cur)) && (!isnan(cr_ref)) &&
                (fabsf(cr_cur) > EPSF) && (fabsf(cr_ref) > EPSF) &&
                (ratio > EPSF);
    float s = cond ? sqrtf(fabsf(ratio)) : 1.0f;
    if (!isfinite(s)) s = 1.0f;  // 'ok' guard
    return s;
}

// cr over 4 rows in smem, row stride 64 floats
__device__ __forceinline__ float cr_rows(const float* hs, int lane) {
    float sgn = (lane == 31) ? -1.0f : 1.0f;
    float a0 = hs[0 * DD + lane], a1 = hs[0 * DD + lane + 32];
    float b0 = hs[1 * DD + lane], b1 = hs[1 * DD + lane + 32];
    float c0 = hs[2 * DD + lane], c1 = hs[2 * DD + lane + 32];
    float d0 = hs[3 * DD + lane], d1 = hs[3 * DD + lane + 32];
    float hac = warp_reduce_add(a0 * c0 + sgn * a1 * c1);
    float hbd = warp_reduce_add(b0 * d0 + sgn * b1 * d1);
    float had = warp_reduce_add(a0 * d0 + sgn * a1 * d1);
    float hbc = warp_reduce_add(b0 * c0 + sgn * b1 * c1);
    return (hac * hbd) / (had * hbc + EPSF);
}

// 8-lane (tx-group) butterfly sum: lanes differing in bits 0..2
__device__ __forceinline__ float oct_reduce_add(float v) {
    v += __shfl_xor_sync(0xffffffffu, v, 1);
    v += __shfl_xor_sync(0xffffffffu, v, 2);
    v += __shfl_xor_sync(0xffffffffu, v, 4);
    return v;
}

// --------------------------------------------------------------------------
// Single-pass fixed-capacity CSR fill; also resets the publish flag.
// --------------------------------------------------------------------------
__global__ void fill_kernel(const int* __restrict__ src,
                            const int* __restrict__ dst) {
    int e = blockIdx.x * blockDim.x + threadIdx.x;
    if (e == 0) g_flag = 0;
    if (e < EE) {
        int d = __ldg(&dst[e]);
        int p = atomicAdd(&g_cur[d], 1);
        if (p < CAP) g_csr[d * CAP + p] = __ldg(&src[e]);
    }
}

// --------------------------------------------------------------------------
// gemm0: g_h0h = half(normalize(X @ W0 + b0)); block 0 stores cr_init & cr0.
// 128 rows x 64 cols per block, 128 threads, 8x8 micro-tile, FFMA2.
// --------------------------------------------------------------------------
__global__ void __launch_bounds__(128, 3)
gemm0_kernel(const float* __restrict__ Xin, const float* __restrict__ W,
             const float* __restrict__ B) {
    extern __shared__ float smdyn[];
    float (*ws)[64] = (float(*)[64])smdyn;               // 64x64
    float (*xs)[64] = (float(*)[64])(smdyn + 4096);      // 128x64
    float (*crbuf)[64] = (float(*)[64])(smdyn + 12288);  // 4x64

    int tid = threadIdx.x;
    int rbase = blockIdx.x * 128;

#pragma unroll
    for (int i = 0; i < 8; i++) {
        int idx = tid + i * 128;
        ((float4*)ws)[idx] = ((const float4*)W)[idx];
    }
#pragma unroll
    for (int i = 0; i < 16; i++) {
        int idx = tid + i * 128;
        int rr = idx >> 4, kk = (idx & 15) * 4;
        int gr = rbase + rr;
        float4 v = make_float4(0.f, 0.f, 0.f, 0.f);
        if (gr < NN) v = *(const float4*)&Xin[gr * DD + kk];
        *(float4*)&xs[rr][kk] = v;
    }
    __syncthreads();

    int ty = tid >> 3;  // 0..15, rows ty*8..+7
    int tx = tid & 7;   // cols tx*8..+7

    unsigned long long accp[8][4];
#pragma unroll
    for (int i = 0; i < 8; i++)
#pragma unroll
        for (int j = 0; j < 4; j++) accp[i][j] = 0ull;

#pragma unroll
    for (int k0 = 0; k0 < 64; k0 += 4) {
        float4 xv4[8];
#pragma unroll
        for (int i = 0; i < 8; i++)
            xv4[i] = *(const float4*)&xs[ty * 8 + i][k0];
#pragma unroll
        for (int kk = 0; kk < 4; kk++) {
            ulonglong2 wa = *(const ulonglong2*)&ws[k0 + kk][tx * 8];
            ulonglong2 wb = *(const ulonglong2*)&ws[k0 + kk][tx * 8 + 4];
#pragma unroll
            for (int i = 0; i < 8; i++) {
                unsigned xb = __float_as_uint((&xv4[i].x)[kk]);
                unsigned long long x2;
                PACK_F32X2(x2, xb, xb);
                FMA_F32X2(accp[i][0], x2, wa.x, accp[i][0]);
                FMA_F32X2(accp[i][1], x2, wa.y, accp[i][1]);
                FMA_F32X2(accp[i][2], x2, wb.x, accp[i][2]);
                FMA_F32X2(accp[i][3], x2, wb.y, accp[i][3]);
            }
        }
    }

    float4 ba = *(const float4*)&B[tx * 8];
    float4 bb = *(const float4*)&B[tx * 8 + 4];

#pragma unroll
    for (int i = 0; i < 8; i++) {
        int gr = rbase + ty * 8 + i;
        float v[8];
#pragma unroll
        for (int j = 0; j < 4; j++) {
            unsigned lo, hi;
            UNPACK_F32X2(lo, hi, accp[i][j]);
            v[j * 2 + 0] = __uint_as_float(lo);
            v[j * 2 + 1] = __uint_as_float(hi);
        }
        v[0] += ba.x; v[1] += ba.y; v[2] += ba.z; v[3] += ba.w;
        v[4] += bb.x; v[5] += bb.y; v[6] += bb.z; v[7] += bb.w;
        float ss = 0.f;
#pragma unroll
        for (int j = 0; j < 8; j++) ss += v[j] * v[j];
        ss = oct_reduce_add(ss);
        float inv = 1.f / (sqrtf(ss) + EPSF);
#pragma unroll
        for (int j = 0; j < 8; j++) v[j] *= inv;
        if (gr < NN) {
            __half2 h01 = __floats2half2_rn(v[0], v[1]);
            __half2 h23 = __floats2half2_rn(v[2], v[3]);
            __half2 h45 = __floats2half2_rn(v[4], v[5]);
            __half2 h67 = __floats2half2_rn(v[6], v[7]);
            uint4 u;
            u.x = *(unsigned*)&h01; u.y = *(unsigned*)&h23;
            u.z = *(unsigned*)&h45; u.w = *(unsigned*)&h67;
            *(uint4*)&g_h0h[gr * DD + tx * 8] = u;
        }
        if (blockIdx.x == 0 && ty == 0 && i < 4) {
#pragma unroll
            for (int j = 0; j < 8; j++) crbuf[i][tx * 8 + j] = v[j];
        }
    }

    if (blockIdx.x == 0) {
        __syncthreads();
        if (tid < 32) {
            float cr = cr_rows(&crbuf[0][0], tid);
            if (tid == 0) g_scalars[3] = cr;   // cr0 (of h0)
        } else if (tid < 64) {
            float cr = cr_rows(&xs[0][0], tid - 32);
            if (tid == 32) g_scalars[0] = cr;  // cr_init (of x)
        }
    }
}

// --------------------------------------------------------------------------
// Fused gemm12 (128 rows/block, 128 threads, 8x8 micro):
//   agg = fp16 CSR gather-sum of g_h0h  -> xs
//   hm  = normalize((agg @ Wm)/deg + bm) -> xs (in place, via regs)
//   out = sf * relu(normalize(sm*(hm @ W1) + b1))
// Block 0 computes sm (after pass 1) and sf (after pass 2) from rows 0..3
// and publishes via g_flag; other blocks spin just before their epilogue.
// --------------------------------------------------------------------------
__global__ void __launch_bounds__(128, 3)
gemm12_kernel(const float* __restrict__ Wm, const float* __restrict__ bm,
              const float* __restrict__ W1, const float* __restrict__ b1,
              float* __restrict__ Yout) {
    extern __shared__ float smdyn[];
    float (*wsm)[64] = (float(*)[64])smdyn;               // 64x64
    float (*ws1)[64] = (float(*)[64])(smdyn + 4096);      // 64x64
    float (*xs)[64] = (float(*)[64])(smdyn + 8192);       // 128x64
    float (*crbuf)[64] = (float(*)[64])(smdyn + 16384);   // 4x64
    float* s_scal = smdyn + 16640;                        // [0]=sm [1]=sf

    int tid = threadIdx.x;
    int rbase = blockIdx.x * 128;

#pragma unroll
    for (int i = 0; i < 8; i++) {
        int idx = tid + i * 128;
        ((float4*)wsm)[idx] = ((const float4*)Wm)[idx];
        ((float4*)ws1)[idx] = ((const float4*)W1)[idx];
    }

    // Fused fp16 gather: 16 groups of 8 threads; group handles rows
    // it*16+grp; thread q loads 16B of the 128B row.
    {
        int grp = tid >> 3;
        int q = tid & 7;
#pragma unroll
        for (int it = 0; it < 8; it++) {
            int rr = it * 16 + grp;
            int n = rbase + rr;
            float a[8];
#pragma unroll
            for (int j = 0; j < 8; j++) a[j] = 0.f;
            if (n < NN) {
                int dg = min(g_cur[n], CAP);
                const int* lst = &g_csr[n * CAP];
                const __half* tb = g_h0h;
                int i = 0;
                for (; i + 4 <= dg; i += 4) {
                    int s0 = lst[i + 0];
                    int s1 = lst[i + 1];
                    int s2 = lst[i + 2];
                    int s3 = lst[i + 3];
                    uint4 r0 = *(const uint4*)&tb[s0 * DD + q * 8];
                    uint4 r1 = *(const uint4*)&tb[s1 * DD + q * 8];
                    uint4 r2 = *(const uint4*)&tb[s2 * DD + q * 8];
                    uint4 r3 = *(const uint4*)&tb[s3 * DD + q * 8];
#pragma unroll
                    for (int c = 0; c < 4; c++) {
                        unsigned u0 = (&r0.x)[c], u1 = (&r1.x)[c];
                        unsigned u2 = (&r2.x)[c], u3 = (&r3.x)[c];
                        float2 f0 = __half22float2(*(__half2*)&u0);
                        float2 f1 = __half22float2(*(__half2*)&u1);
                        float2 f2 = __half22float2(*(__half2*)&u2);
                        float2 f3 = __half22float2(*(__half2*)&u3);
                        a[c * 2 + 0] += (f0.x + f1.x) + (f2.x + f3.x);
                        a[c * 2 + 1] += (f0.y + f1.y) + (f2.y + f3.y);
                    }
                }
                for (; i < dg; i++) {
                    int s0 = lst[i];
                    uint4 r0 = *(const uint4*)&tb[s0 * DD + q * 8];
#pragma unroll
                    for (int c = 0; c < 4; c++) {
                        unsigned u0 = (&r0.x)[c];
                        float2 f0 = __half22float2(*(__half2*)&u0);
                        a[c * 2 + 0] += f0.x;
                        a[c * 2 + 1] += f0.y;
                    }
                }
            }
            *(float4*)&xs[rr][q * 8 + 0] = make_float4(a[0], a[1], a[2], a[3]);
            *(float4*)&xs[rr][q * 8 + 4] = make_float4(a[4], a[5], a[6], a[7]);
        }
    }
    __syncthreads();

    int ty = tid >> 3;
    int tx = tid & 7;

    unsigned long long accp[8][4];
#pragma unroll
    for (int i = 0; i < 8; i++)
#pragma unroll
        for (int j = 0; j < 4; j++) accp[i][j] = 0ull;

    // ---- pass 1: agg @ Wm ----
#pragma unroll
    for (int k0 = 0; k0 < 64; k0 += 4) {
        float4 xv4[8];
#pragma unroll
        for (int i = 0; i < 8; i++)
            xv4[i] = *(const float4*)&xs[ty * 8 + i][k0];
#pragma unroll
        for (int kk = 0; kk < 4; kk++) {
            ulonglong2 wa = *(const ulonglong2*)&wsm[k0 + kk][tx * 8];
            ulonglong2 wb = *(const ulonglong2*)&wsm[k0 + kk][tx * 8 + 4];
#pragma unroll
            for (int i = 0; i < 8; i++) {
                unsigned xb = __float_as_uint((&xv4[i].x)[kk]);
                unsigned long long x2;
                PACK_F32X2(x2, xb, xb);
                FMA_F32X2(accp[i][0], x2, wa.x, accp[i][0]);
                FMA_F32X2(accp[i][1], x2, wa.y, accp[i][1]);
                FMA_F32X2(accp[i][2], x2, wb.x, accp[i][2]);
                FMA_F32X2(accp[i][3], x2, wb.y, accp[i][3]);
            }
        }
    }

    // pass-1 epilogue: hm = normalize(acc/deg + bm), packed back into accp
    {
        float4 ba = *(const float4*)&bm[tx * 8];
        float4 bb = *(const float4*)&bm[tx * 8 + 4];
#pragma unroll
        for (int i = 0; i < 8; i++) {
            int gr = rbase + ty * 8 + i;
            float c = (gr < NN) ? (float)min(g_cur[gr], CAP) : 1.f;
            float rs = 1.f / fmaxf(c, 1.f);
            float v[8];
#pragma unroll
            for (int j = 0; j < 4; j++) {
                unsigned lo, hi;
                UNPACK_F32X2(lo, hi, accp[i][j]);
                v[j * 2 + 0] = __uint_as_float(lo);
                v[j * 2 + 1] = __uint_as_float(hi);
            }
            v[0] = fmaf(v[0], rs, ba.x); v[1] = fmaf(v[1], rs, ba.y);
            v[2] = fmaf(v[2], rs, ba.z); v[3] = fmaf(v[3], rs, ba.w);
            v[4] = fmaf(v[4], rs, bb.x); v[5] = fmaf(v[5], rs, bb.y);
            v[6] = fmaf(v[6], rs, bb.z); v[7] = fmaf(v[7], rs, bb.w);
            float ss = 0.f;
#pragma unroll
            for (int j = 0; j < 8; j++) ss += v[j] * v[j];
            ss = oct_reduce_add(ss);
            float inv = 1.f / (sqrtf(ss) + EPSF);
#pragma unroll
            for (int j = 0; j < 8; j++) v[j] *= inv;
#pragma unroll
            for (int j = 0; j < 4; j++)
                PACK_F32X2(accp[i][j], __float_as_uint(v[j * 2]),
                           __float_as_uint(v[j * 2 + 1]));
        }
    }

    __syncthreads();  // everyone done reading xs (agg)
    // store hm into xs
#pragma unroll
    for (int i = 0; i < 8; i++) {
        unsigned l0, h0, l1, h1, l2, h2, l3, h3;
        UNPACK_F32X2(l0, h0, accp[i][0]);
        UNPACK_F32X2(l1, h1, accp[i][1]);
        UNPACK_F32X2(l2, h2, accp[i][2]);
        UNPACK_F32X2(l3, h3, accp[i][3]);
        *(float4*)&xs[ty * 8 + i][tx * 8] =
            make_float4(__uint_as_float(l0), __uint_as_float(h0),
                        __uint_as_float(l1), __uint_as_float(h1));
        *(float4*)&xs[ty * 8 + i][tx * 8 + 4] =
            make_float4(__uint_as_float(l2), __uint_as_float(h2),
                        __uint_as_float(l3), __uint_as_float(h3));
    }
    __syncthreads();

    // block 0: scale_m from hm rows 0..3
    if (blockIdx.x == 0) {
        if (tid < 32) {
            float cr = cr_rows(&xs[0][0], tid);
            if (tid == 0) {
                float sc = compute_scale(cr, g_scalars[3]);
                g_scalars[1] = sc;
                s_scal[0] = sc;
            }
        }
        __syncthreads();
    }

    // ---- pass 2: hm @ W1 ----
#pragma unroll
    for (int i = 0; i < 8; i++)
#pragma unroll
        for (int j = 0; j < 4; j++) accp[i][j] = 0ull;
#pragma unroll
    for (int k0 = 0; k0 < 64; k0 += 4) {
        float4 xv4[8];
#pragma unroll
        for (int i = 0; i < 8; i++)
            xv4[i] = *(const float4*)&xs[ty * 8 + i][k0];
#pragma unroll
        for (int kk = 0; kk < 4; kk++) {
            ulonglong2 wa = *(const ulonglong2*)&ws1[k0 + kk][tx * 8];
            ulonglong2 wb = *(const ulonglong2*)&ws1[k0 + kk][tx * 8 + 4];
#pragma unroll
            for (int i = 0; i < 8; i++) {
                unsigned xb = __float_as_uint((&xv4[i].x)[kk]);
                unsigned long long x2;
                PACK_F32X2(x2, xb, xb);
                FMA_F32X2(accp[i][0], x2, wa.x, accp[i][0]);
                FMA_F32X2(accp[i][1], x2, wa.y, accp[i][1]);
                FMA_F32X2(accp[i][2], x2, wb.x, accp[i][2]);
                FMA_F32X2(accp[i][3], x2, wb.y, accp[i][3]);
            }
        }
    }

    float4 ba = *(const float4*)&b1[tx * 8];
    float4 bb = *(const float4*)&b1[tx * 8 + 4];

    if (blockIdx.x == 0) {
        float smv = s_scal[0];
        // compute normalized relu rows (pre-sf), repack into accp;
        // rows 0..3 also staged for cross-ratio
#pragma unroll
        for (int i = 0; i < 8; i++) {
            float v[8];
#pragma unroll
            for (int j = 0; j < 4; j++) {
                unsigned lo, hi;
                UNPACK_F32X2(lo, hi, accp[i][j]);
                v[j * 2 + 0] = __uint_as_float(lo);
                v[j * 2 + 1] = __uint_as_float(hi);
            }
            v[0] = fmaf(smv, v[0], ba.x); v[1] = fmaf(smv, v[1], ba.y);
            v[2] = fmaf(smv, v[2], ba.z); v[3] = fmaf(smv, v[3], ba.w);
            v[4] = fmaf(smv, v[4], bb.x); v[5] = fmaf(smv, v[5], bb.y);
            v[6] = fmaf(smv, v[6], bb.z); v[7] = fmaf(smv, v[7], bb.w);
            float ss = 0.f;
#pragma unroll
            for (int j = 0; j < 8; j++) ss += v[j] * v[j];
            ss = oct_reduce_add(ss);
            float inv = 1.f / (sqrtf(ss) + EPSF);
#pragma unroll
            for (int j = 0; j < 8; j++) v[j] = fmaxf(v[j] * inv, 0.f);
            if (ty == 0 && i < 4) {
#pragma unroll
                for (int j = 0; j < 8; j++) crbuf[i][tx * 8 + j] = v[j];
            }
#pragma unroll
            for (int j = 0; j < 4; j++)
                PACK_F32X2(accp[i][j], __float_as_uint(v[j * 2]),
                           __float_as_uint(v[j * 2 + 1]));
        }
        __syncthreads();
        if (tid < 32) {
            float cr = cr_rows(&crbuf[0][0], tid);
            if (tid == 0) {
                float sf = compute_scale(cr, g_scalars[0]);
                g_scalars[2] = sf;
                s_scal[1] = sf;
                __threadfence();
                *(volatile int*)&g_flag = 1;   // publish
            }
        }
        __syncthreads();
        float sfv = s_scal[1];
#pragma unroll
        for (int i = 0; i < 8; i++) {
            int gr = rbase + ty * 8 + i;
            if (gr >= NN) continue;
            float v[8];
#pragma unroll
            for (int j = 0; j < 4; j++) {
                unsigned lo, hi;
                UNPACK_F32X2(lo, hi, accp[i][j]);
                v[j * 2 + 0] = __uint_as_float(lo) * sfv;
                v[j * 2 + 1] = __uint_as_float(hi) * sfv;
            }
            *(float4*)&Yout[gr * DD + tx * 8] =
                make_float4(v[0], v[1], v[2], v[3]);
            *(float4*)&Yout[gr * DD + tx * 8 + 4] =
                make_float4(v[4], v[5], v[6], v[7]);
        }
    } else {
        // wait for block 0 to publish the scales
        if (tid == 0) {
            while (*(volatile int*)&g_flag == 0) { __nanosleep(64); }
            __threadfence();
            s_scal[0] = *(volatile float*)&g_scalars[1];
            s_scal[1] = *(volatile float*)&g_scalars[2];
        }
        __syncthreads();
        float smv = s_scal[0];
        float sfv = s_scal[1];
#pragma unroll
        for (int i = 0; i < 8; i++) {
            int gr = rbase + ty * 8 + i;
            float v[8];
#pragma unroll
            for (int j = 0; j < 4; j++) {
                unsigned lo, hi;
                UNPACK_F32X2(lo, hi, accp[i][j]);
                v[j * 2 + 0] = __uint_as_float(lo);
                v[j * 2 + 1] = __uint_as_float(hi);
            }
            v[0] = fmaf(smv, v[0], ba.x); v[1] = fmaf(smv, v[1], ba.y);
            v[2] = fmaf(smv, v[2], ba.z); v[3] = fmaf(smv, v[3], ba.w);
            v[4] = fmaf(smv, v[4], bb.x); v[5] = fmaf(smv, v[5], bb.y);
            v[6] = fmaf(smv, v[6], bb.z); v[7] = fmaf(smv, v[7], bb.w);
            float ss = 0.f;
#pragma unroll
            for (int j = 0; j < 8; j++) ss += v[j] * v[j];
            ss = oct_reduce_add(ss);
            float inv = 1.f / (sqrtf(ss) + EPSF);
#pragma unroll
            for (int j = 0; j < 8; j++) v[j] = fmaxf(v[j] * inv, 0.f) * sfv;
            if (gr < NN) {
                *(float4*)&Yout[gr * DD + tx * 8] =
                    make_float4(v[0], v[1], v[2], v[3]);
                *(float4*)&Yout[gr * DD + tx * 8 + 4] =
                    make_float4(v[4], v[5], v[6], v[7]);
            }
        }
    }
}

// --------------------------------------------------------------------------
extern "C" void kernel_launch(void* const* d_in, const int* in_sizes, int n_in,
                              void* d_out, int out_size) {
    const float* x  = (const float*)d_in[0];
    const int*  ei  = (const int*)d_in[1];
    const float* W0 = (const float*)d_in[2];
    const float* b0 = (const float*)d_in[3];
    const float* Wm = (const float*)d_in[4];
    const float* bm = (const float*)d_in[5];
    const float* W1 = (const float*)d_in[6];
    const float* b1 = (const float*)d_in[7];
    float* out = (float*)d_out;
    const int* src = ei;
    const int* dst = ei + EE;

    const int gblocks = (NN + 127) / 128;   // 782
    const int eblocks = (EE + 255) / 256;
    const int SMEM0 = (4096 + 8192 + 256) * 4;           // 50176
    const int SMEM12 = (4096 + 4096 + 8192 + 256 + 8) * 4;  // 66592

    // one-time host objects (host-side only; identical work every call)
    static cudaStream_t s2 = nullptr;
    static cudaEvent_t evF, evA;
    static void* curp = nullptr;
    if (!s2) {
        cudaStreamCreateWithFlags(&s2, cudaStreamNonBlocking);
        cudaEventCreateWithFlags(&evF, cudaEventDisableTiming);
        cudaEventCreateWithFlags(&evA, cudaEventDisableTiming);
        cudaGetSymbolAddress(&curp, g_cur);
        cudaFuncSetAttribute(gemm0_kernel,
                             cudaFuncAttributeMaxDynamicSharedMemorySize,
                             SMEM0);
        cudaFuncSetAttribute(gemm12_kernel,
                             cudaFuncAttributeMaxDynamicSharedMemorySize,
                             SMEM12);
    }

    cudaStream_t s0 = 0;  // capture stream

    // fork: gemm0 on s2, concurrent with CSR build on s0
    cudaEventRecord(evF, s0);
    cudaStreamWaitEvent(s2, evF, 0);
    gemm0_kernel<<<gblocks, 128, SMEM0, s2>>>(x, W0, b0);
    cudaEventRecord(evA, s2);

    // CSR build on s0
    cudaMemsetAsync(curp, 0, NN * sizeof(int), s0);
    fill_kernel<<<eblocks, 256, 0, s0>>>(src, dst);

    // fused gemm1+gemm2 (+ inline scale computation) on s0
    cudaStreamWaitEvent(s0, evA, 0);
    gemm12_kernel<<<gblocks, 128, SMEM12, s0>>>(Wm, bm, W1, b1, out);
}

// round 7
// speedup vs baseline: 1.2438x; 1.2438x over previous
#include <cuda_runtime.h>
#include <cuda_fp16.h>
#include <cstdint>
#include <math.h>

#define NN 100000
#define DD 64
#define EE 1600000
#define EPSF 1e-8f
#define CAP 64   // fixed CSR capacity per node (deg ~ Poisson(16); P(>64)~1e-19)

// Scratch (static device globals — no allocation)
__device__ __align__(16) __half g_h0h[NN * DD];   // h0 in fp16 (gather table)
__device__ int g_cur[NN];                         // slot cursor == degree
__device__ int g_csr[NN * CAP];
// [0]=cr_init, [1]=scale_m, [2]=scale_fin, [3]=cr0
__device__ float g_scalars[4];

// ---- packed f32x2 helpers (FFMA2) ----
#define FMA_F32X2(d, a, b, c) \
    asm("fma.rn.f32x2 %0, %1, %2, %3;" : "=l"(d) : "l"(a), "l"(b), "l"(c))
#define PACK_F32X2(out, lo, hi) \
    asm("mov.b64 %0, {%1, %2};" : "=l"(out) : "r"(lo), "r"(hi))
#define UNPACK_F32X2(lo, hi, in) \
    asm("mov.b64 {%0, %1}, %2;" : "=r"(lo), "=r"(hi) : "l"(in))

__device__ __forceinline__ float warp_reduce_add(float v) {
#pragma unroll
    for (int o = 16; o; o >>= 1) v += __shfl_xor_sync(0xffffffffu, v, o);
    return v;
}

// 16-lane group sum (lanes differing in bits 0..3)
__device__ __forceinline__ float hex_reduce_add(float v) {
    v += __shfl_xor_sync(0xffffffffu, v, 1);
    v += __shfl_xor_sync(0xffffffffu, v, 2);
    v += __shfl_xor_sync(0xffffffffu, v, 4);
    v += __shfl_xor_sync(0xffffffffu, v, 8);
    return v;
}

__device__ __forceinline__ float compute_scale(float cr_cur, float cr_ref) {
    float ratio = cr_ref / (cr_cur + EPSF);
    bool cond = (!isnan(cr_cur)) && (!isnan(cr_ref)) &&
                (fabsf(cr_cur) > EPSF) && (fabsf(cr_ref) > EPSF) &&
                (ratio > EPSF);
    float s = cond ? sqrtf(fabsf(ratio)) : 1.0f;
    if (!isfinite(s)) s = 1.0f;  // 'ok' guard
    return s;
}

// cr over 4 rows in smem, row stride 64 floats
__device__ __forceinline__ float cr_rows(const float* hs, int lane) {
    float sgn = (lane == 31) ? -1.0f : 1.0f;
    float a0 = hs[0 * DD + lane], a1 = hs[0 * DD + lane + 32];
    float b0 = hs[1 * DD + lane], b1 = hs[1 * DD + lane + 32];
    float c0 = hs[2 * DD + lane], c1 = hs[2 * DD + lane + 32];
    float d0 = hs[3 * DD + lane], d1 = hs[3 * DD + lane + 32];
    float hac = warp_reduce_add(a0 * c0 + sgn * a1 * c1);
    float hbd = warp_reduce_add(b0 * d0 + sgn * b1 * d1);
    float had = warp_reduce_add(a0 * d0 + sgn * a1 * d1);
    float hbc = warp_reduce_add(b0 * c0 + sgn * b1 * c1);
    return (hac * hbd) / (had * hbc + EPSF);
}

// --------------------------------------------------------------------------
// Single-pass fixed-capacity CSR fill.
// --------------------------------------------------------------------------
__global__ void fill_kernel(const int* __restrict__ src,
                            const int* __restrict__ dst) {
    int e = blockIdx.x * blockDim.x + threadIdx.x;
    if (e < EE) {
        int d = __ldg(&dst[e]);
        int p = atomicAdd(&g_cur[d], 1);
        if (p < CAP) g_csr[d * CAP + p] = __ldg(&src[e]);
    }
}

// --------------------------------------------------------------------------
// Shared inner product: 8 rows x 4 cols per thread, k-chunk 2, FFMA2.
// xs: [128][64], ws: [64][64]. ty=tid>>4 (0..15), tx=tid&15.
// --------------------------------------------------------------------------
__device__ __forceinline__ void mm_8x4(const float (*xs)[64],
                                       const float (*ws)[64],
                                       int ty, int tx,
                                       unsigned long long accp[8][2]) {
#pragma unroll
    for (int i = 0; i < 8; i++) { accp[i][0] = 0ull; accp[i][1] = 0ull; }
#pragma unroll
    for (int k0 = 0; k0 < 64; k0 += 2) {
        float2 xv[8];
#pragma unroll
        for (int i = 0; i < 8; i++)
            xv[i] = *(const float2*)&xs[ty * 8 + i][k0];
#pragma unroll
        for (int kk = 0; kk < 2; kk++) {
            ulonglong2 w2 = *(const ulonglong2*)&ws[k0 + kk][tx * 4];
#pragma unroll
            for (int i = 0; i < 8; i++) {
                unsigned xb = __float_as_uint(kk ? xv[i].y : xv[i].x);
                unsigned long long x2;
                PACK_F32X2(x2, xb, xb);
                FMA_F32X2(accp[i][0], x2, w2.x, accp[i][0]);
                FMA_F32X2(accp[i][1], x2, w2.y, accp[i][1]);
            }
        }
    }
}

// --------------------------------------------------------------------------
// gemm0: g_h0h = half(normalize(X @ W0 + b0)); block 0 stores cr_init & cr0.
// 128 rows x 64 cols per block, 256 threads, 8x4 micro-tile.
// --------------------------------------------------------------------------
__global__ void __launch_bounds__(256, 3)
gemm0_kernel(const float* __restrict__ Xin, const float* __restrict__ W,
             const float* __restrict__ B) {
    extern __shared__ float smdyn[];
    float (*ws)[64] = (float(*)[64])smdyn;               // 64x64 (16KB)
    float (*xs)[64] = (float(*)[64])(smdyn + 4096);      // 128x64 (32KB)
    float (*crbuf)[64] = (float(*)[64])(smdyn + 12288);  // 4x64 (1KB)

    int tid = threadIdx.x;
    int rbase = blockIdx.x * 128;

#pragma unroll
    for (int i = 0; i < 4; i++) {
        int idx = tid + i * 256;
        ((float4*)ws)[idx] = ((const float4*)W)[idx];
    }
#pragma unroll
    for (int i = 0; i < 8; i++) {
        int idx = tid + i * 256;
        int rr = idx >> 4, kk = (idx & 15) * 4;
        int gr = rbase + rr;
        float4 v = make_float4(0.f, 0.f, 0.f, 0.f);
        if (gr < NN) v = *(const float4*)&Xin[gr * DD + kk];
        *(float4*)&xs[rr][kk] = v;
    }
    __syncthreads();

    int ty = tid >> 4;
    int tx = tid & 15;

    unsigned long long accp[8][2];
    mm_8x4(xs, ws, ty, tx, accp);

    float4 b4 = *(const float4*)&B[tx * 4];
#pragma unroll
    for (int i = 0; i < 8; i++) {
        int gr = rbase + ty * 8 + i;
        unsigned a0u, a1u, a2u, a3u;
        UNPACK_F32X2(a0u, a1u, accp[i][0]);
        UNPACK_F32X2(a2u, a3u, accp[i][1]);
        float v0 = __uint_as_float(a0u) + b4.x;
        float v1 = __uint_as_float(a1u) + b4.y;
        float v2 = __uint_as_float(a2u) + b4.z;
        float v3 = __uint_as_float(a3u) + b4.w;
        float ss = v0 * v0 + v1 * v1 + v2 * v2 + v3 * v3;
        ss = hex_reduce_add(ss);
        float inv = 1.f / (sqrtf(ss) + EPSF);
        v0 *= inv; v1 *= inv; v2 *= inv; v3 *= inv;
        if (gr < NN) {
            __half2 p01 = __floats2half2_rn(v0, v1);
            __half2 p23 = __floats2half2_rn(v2, v3);
            uint2 st;
            st.x = *(unsigned*)&p01;
            st.y = *(unsigned*)&p23;
            *(uint2*)&g_h0h[gr * DD + tx * 4] = st;
        }
        if (blockIdx.x == 0 && ty == 0 && i < 4) {
            crbuf[i][tx * 4 + 0] = v0;
            crbuf[i][tx * 4 + 1] = v1;
            crbuf[i][tx * 4 + 2] = v2;
            crbuf[i][tx * 4 + 3] = v3;
        }
    }

    if (blockIdx.x == 0) {
        __syncthreads();
        if (tid < 32) {
            float cr = cr_rows(&crbuf[0][0], tid);
            if (tid == 0) g_scalars[3] = cr;   // cr0 (of h0)
        } else if (tid < 64) {
            float cr = cr_rows(&xs[0][0], tid - 32);
            if (tid == 32) g_scalars[0] = cr;  // cr_init (of x)
        }
    }
}

// --------------------------------------------------------------------------
// Fused gemm12 (128 rows/block, 256 threads, 8x4 micro):
//   agg = fp16 CSR gather-sum of g_h0h  -> xs
//   hm  = normalize((agg @ Wm)/deg + bm) -> xs (via regs)
//   out = sf * relu(normalize(sm*(hm @ W1) + b1))
// Scales sm/sf precomputed by small4 (stream-ordered before this kernel).
// --------------------------------------------------------------------------
__global__ void __launch_bounds__(256, 3)
gemm12_kernel(const float* __restrict__ Wm, const float* __restrict__ bm,
              const float* __restrict__ W1, const float* __restrict__ b1,
              float* __restrict__ Yout) {
    extern __shared__ float smdyn[];
    float (*wsm)[64] = (float(*)[64])smdyn;               // 64x64
    float (*ws1)[64] = (float(*)[64])(smdyn + 4096);      // 64x64
    float (*xs)[64] = (float(*)[64])(smdyn + 8192);       // 128x64

    int tid = threadIdx.x;
    int rbase = blockIdx.x * 128;

#pragma unroll
    for (int i = 0; i < 4; i++) {
        int idx = tid + i * 256;
        ((float4*)wsm)[idx] = ((const float4*)Wm)[idx];
        ((float4*)ws1)[idx] = ((const float4*)W1)[idx];
    }

    // Fused fp16 gather: 32 groups of 8 threads; group handles row
    // it*32+grp; thread q loads 16B (8 halfs) of the 128B row.
    {
        int grp = tid >> 3;
        int q = tid & 7;
#pragma unroll
        for (int it = 0; it < 4; it++) {
            int rr = it * 32 + grp;
            int n = rbase + rr;
            float a[8];
#pragma unroll
            for (int j = 0; j < 8; j++) a[j] = 0.f;
            if (n < NN) {
                int dg = min(g_cur[n], CAP);
                const int* lst = &g_csr[n * CAP];
                const __half* tb = g_h0h;
                int i = 0;
                for (; i + 4 <= dg; i += 4) {
                    int s0 = lst[i + 0];
                    int s1 = lst[i + 1];
                    int s2 = lst[i + 2];
                    int s3 = lst[i + 3];
                    uint4 r0 = *(const uint4*)&tb[s0 * DD + q * 8];
                    uint4 r1 = *(const uint4*)&tb[s1 * DD + q * 8];
                    uint4 r2 = *(const uint4*)&tb[s2 * DD + q * 8];
                    uint4 r3 = *(const uint4*)&tb[s3 * DD + q * 8];
#pragma unroll
                    for (int c = 0; c < 4; c++) {
                        unsigned u0 = (&r0.x)[c], u1 = (&r1.x)[c];
                        unsigned u2 = (&r2.x)[c], u3 = (&r3.x)[c];
                        float2 f0 = __half22float2(*(__half2*)&u0);
                        float2 f1 = __half22float2(*(__half2*)&u1);
                        float2 f2 = __half22float2(*(__half2*)&u2);
                        float2 f3 = __half22float2(*(__half2*)&u3);
                        a[c * 2 + 0] += (f0.x + f1.x) + (f2.x + f3.x);
                        a[c * 2 + 1] += (f0.y + f1.y) + (f2.y + f3.y);
                    }
                }
                for (; i < dg; i++) {
                    int s0 = lst[i];
                    uint4 r0 = *(const uint4*)&tb[s0 * DD + q * 8];
#pragma unroll
                    for (int c = 0; c < 4; c++) {
                        unsigned u0 = (&r0.x)[c];
                        float2 f0 = __half22float2(*(__half2*)&u0);
                        a[c * 2 + 0] += f0.x;
                        a[c * 2 + 1] += f0.y;
                    }
                }
            }
            *(float4*)&xs[rr][q * 8 + 0] = make_float4(a[0], a[1], a[2], a[3]);
            *(float4*)&xs[rr][q * 8 + 4] = make_float4(a[4], a[5], a[6], a[7]);
        }
    }
    __syncthreads();

    int ty = tid >> 4;
    int tx = tid & 15;

    // ---- pass 1: agg @ Wm ----
    unsigned long long accp[8][2];
    mm_8x4(xs, wsm, ty, tx, accp);

    // pass-1 epilogue: hm = normalize(acc/deg + bm), repacked into accp
    {
        float4 ba = *(const float4*)&bm[tx * 4];
#pragma unroll
        for (int i = 0; i < 8; i++) {
            int gr = rbase + ty * 8 + i;
            float c = (gr < NN) ? (float)min(g_cur[gr], CAP) : 1.f;
            float rs = 1.f / fmaxf(c, 1.f);
            unsigned a0u, a1u, a2u, a3u;
            UNPACK_F32X2(a0u, a1u, accp[i][0]);
            UNPACK_F32X2(a2u, a3u, accp[i][1]);
            float v0 = fmaf(__uint_as_float(a0u), rs, ba.x);
            float v1 = fmaf(__uint_as_float(a1u), rs, ba.y);
            float v2 = fmaf(__uint_as_float(a2u), rs, ba.z);
            float v3 = fmaf(__uint_as_float(a3u), rs, ba.w);
            float ss = v0 * v0 + v1 * v1 + v2 * v2 + v3 * v3;
            ss = hex_reduce_add(ss);
            float inv = 1.f / (sqrtf(ss) + EPSF);
            PACK_F32X2(accp[i][0], __float_as_uint(v0 * inv),
                       __float_as_uint(v1 * inv));
            PACK_F32X2(accp[i][1], __float_as_uint(v2 * inv),
                       __float_as_uint(v3 * inv));
        }
    }

    __syncthreads();  // everyone done reading xs (agg)
#pragma unroll
    for (int i = 0; i < 8; i++) {
        unsigned l0, h0, l1, h1;
        UNPACK_F32X2(l0, h0, accp[i][0]);
        UNPACK_F32X2(l1, h1, accp[i][1]);
        *(float4*)&xs[ty * 8 + i][tx * 4] =
            make_float4(__uint_as_float(l0), __uint_as_float(h0),
                        __uint_as_float(l1), __uint_as_float(h1));
    }
    __syncthreads();

    // ---- pass 2: hm @ W1 ----
    mm_8x4(xs, ws1, ty, tx, accp);

    float4 b14 = *(const float4*)&b1[tx * 4];
    float sm = g_scalars[1];
    float sf = g_scalars[2];
#pragma unroll
    for (int i = 0; i < 8; i++) {
        int gr = rbase + ty * 8 + i;
        unsigned a0u, a1u, a2u, a3u;
        UNPACK_F32X2(a0u, a1u, accp[i][0]);
        UNPACK_F32X2(a2u, a3u, accp[i][1]);
        float v0 = fmaf(sm, __uint_as_float(a0u), b14.x);
        float v1 = fmaf(sm, __uint_as_float(a1u), b14.y);
        float v2 = fmaf(sm, __uint_as_float(a2u), b14.z);
        float v3 = fmaf(sm, __uint_as_float(a3u), b14.w);
        float ss = v0 * v0 + v1 * v1 + v2 * v2 + v3 * v3;
        ss = hex_reduce_add(ss);
        float inv = 1.f / (sqrtf(ss) + EPSF);
        v0 = fmaxf(v0 * inv, 0.f) * sf;
        v1 = fmaxf(v1 * inv, 0.f) * sf;
        v2 = fmaxf(v2 * inv, 0.f) * sf;
        v3 = fmaxf(v3 * inv, 0.f) * sf;
        if (gr < NN)
            *(float4*)&Yout[gr * DD + tx * 4] = make_float4(v0, v1, v2, v3);
    }
}

// --------------------------------------------------------------------------
// Merged small kernel: rows 0..3 of both remaining layers -> scale_m and
// scale_fin. Runs concurrently with nothing heavy; ~4us.
// --------------------------------------------------------------------------
__global__ void small4_kernel(const float* __restrict__ Wm,
                              const float* __restrict__ bm,
                              const float* __restrict__ W1,
                              const float* __restrict__ b1) {
    __shared__ float ins[4][DD];
    __shared__ float hs[4][DD];
    __shared__ float red[8];
    __shared__ float s_scale;
    int tid = threadIdx.x;
    int r = tid >> 6, c = tid & 63;

    // phase A: message rows 0..3 -> hm rows, scale_m
    {
        int dg = min(g_cur[r], CAP);
        const int* lst = &g_csr[r * CAP];
        float s = 0.f;
        for (int i = 0; i < dg; i++)
            s += __half2float(g_h0h[lst[i] * DD + c]);
        ins[r][c] = s / fmaxf((float)dg, 1.f);
    }
    __syncthreads();
    float acc = 0.f;
#pragma unroll
    for (int k = 0; k < 64; k++) acc = fmaf(ins[r][k], Wm[k * DD + c], acc);
    acc += bm[c];
    float ss = acc * acc;
#pragma unroll
    for (int o = 16; o; o >>= 1) ss += __shfl_xor_sync(0xffffffffu, ss, o);
    if ((tid & 31) == 0) red[tid >> 5] = ss;
    __syncthreads();
    float tot = red[r * 2] + red[r * 2 + 1];
    float y = acc / (sqrtf(tot) + EPSF);
    hs[r][c] = y;
    __syncthreads();
    if (tid < 32) {
        float cr_cur = cr_rows(&hs[0][0], tid);
        if (tid == 0) {
            float sc = compute_scale(cr_cur, g_scalars[3]);
            g_scalars[1] = sc;
            s_scale = sc;
        }
    }
    __syncthreads();

    // phase B: final rows 0..3 -> scale_fin
    float accB = 0.f;
#pragma unroll
    for (int k = 0; k < 64; k++) accB = fmaf(hs[r][k], W1[k * DD + c], accB);
    accB = fmaf(s_scale, accB, b1[c]);
    float ssB = accB * accB;
#pragma unroll
    for (int o = 16; o; o >>= 1) ssB += __shfl_xor_sync(0xffffffffu, ssB, o);
    if ((tid & 31) == 0) red[tid >> 5] = ssB;
    __syncthreads();
    float totB = red[r * 2] + red[r * 2 + 1];
    float yB = fmaxf(accB / (sqrtf(totB) + EPSF), 0.f);
    ins[r][c] = yB;   // reuse ins
    __syncthreads();
    if (tid < 32) {
        float cr2 = cr_rows(&ins[0][0], tid);
        if (tid == 0)
            g_scalars[2] = compute_scale(cr2, g_scalars[0]);
    }
}

// --------------------------------------------------------------------------
extern "C" void kernel_launch(void* const* d_in, const int* in_sizes, int n_in,
                              void* d_out, int out_size) {
    const float* x  = (const float*)d_in[0];
    const int*  ei  = (const int*)d_in[1];
    const float* W0 = (const float*)d_in[2];
    const float* b0 = (const float*)d_in[3];
    const float* Wm = (const float*)d_in[4];
    const float* bm = (const float*)d_in[5];
    const float* W1 = (const float*)d_in[6];
    const float* b1 = (const float*)d_in[7];
    float* out = (float*)d_out;
    const int* src = ei;
    const int* dst = ei + EE;

    const int gblocks = (NN + 127) / 128;   // 782
    const int eblocks = (EE + 255) / 256;
    const int SMEM0 = (4096 + 8192 + 256) * 4;       // 50176
    const int SMEM12 = (4096 + 4096 + 8192) * 4;     // 65536

    // one-time host objects (host-side only; identical work every call)
    static cudaStream_t s2 = nullptr;
    static cudaEvent_t evF, evA, evFill, evB;
    static void* curp = nullptr;
    if (!s2) {
        cudaStreamCreateWithFlags(&s2, cudaStreamNonBlocking);
        cudaEventCreateWithFlags(&evF, cudaEventDisableTiming);
        cudaEventCreateWithFlags(&evA, cudaEventDisableTiming);
        cudaEventCreateWithFlags(&evFill, cudaEventDisableTiming);
        cudaEventCreateWithFlags(&evB, cudaEventDisableTiming);
        cudaGetSymbolAddress(&curp, g_cur);
        cudaFuncSetAttribute(gemm0_kernel,
                             cudaFuncAttributeMaxDynamicSharedMemorySize,
                             SMEM0);
        cudaFuncSetAttribute(gemm12_kernel,
                             cudaFuncAttributeMaxDynamicSharedMemorySize,
                             SMEM12);
    }

    cudaStream_t s0 = 0;  // capture stream

    // fork: gemm0 on s2, concurrent with CSR build on s0
    cudaEventRecord(evF, s0);
    cudaStreamWaitEvent(s2, evF, 0);
    gemm0_kernel<<<gblocks, 256, SMEM0, s2>>>(x, W0, b0);
    cudaEventRecord(evA, s2);

    // CSR build on s0
    cudaMemsetAsync(curp, 0, NN * sizeof(int), s0);
    fill_kernel<<<eblocks, 256, 0, s0>>>(src, dst);
    cudaEventRecord(evFill, s0);

    // small4 on s2 (after gemm0 [stream order] + fill)
    cudaStreamWaitEvent(s2, evFill, 0);
    small4_kernel<<<1, 256, 0, s2>>>(Wm, bm, W1, b1);
    cudaEventRecord(evB, s2);

    // fused gemm1+gemm2 on s0 (after fill [stream order] + gemm0 + small4)
    cudaStreamWaitEvent(s0, evA, 0);
    cudaStreamWaitEvent(s0, evB, 0);
    gemm12_kernel<<<gblocks, 256, SMEM12, s0>>>(Wm, bm, W1, b1, out);
}

// round 8
// speedup vs baseline: 1.3257x; 1.0658x over previous
#include <cuda_runtime.h>
#include <cuda_fp16.h>
#include <cstdint>
#include <math.h>

#define NN 100000
#define DD 64
#define EE 1600000
#define EPSF 1e-8f
#define CAP 64   // fixed CSR capacity per node (deg ~ Poisson(16); P(>64)~1e-19)

// Scratch (static device globals — no allocation)
__device__ __align__(16) __half g_h0h[NN * DD];   // h0 in fp16 (gather table)
__device__ int g_cur[NN];                         // slot cursor == degree
__device__ __align__(16) int g_csr[NN * CAP];
// [0]=cr_init, [1]=scale_m, [2]=scale_fin, [3]=cr0
__device__ float g_scalars[4];

// ---- packed f32x2 helpers (FFMA2) ----
#define FMA_F32X2(d, a, b, c) \
    asm("fma.rn.f32x2 %0, %1, %2, %3;" : "=l"(d) : "l"(a), "l"(b), "l"(c))
#define PACK_F32X2(out, lo, hi) \
    asm("mov.b64 %0, {%1, %2};" : "=l"(out) : "r"(lo), "r"(hi))
#define UNPACK_F32X2(lo, hi, in) \
    asm("mov.b64 {%0, %1}, %2;" : "=r"(lo), "=r"(hi) : "l"(in))

__device__ __forceinline__ float warp_reduce_add(float v) {
#pragma unroll
    for (int o = 16; o; o >>= 1) v += __shfl_xor_sync(0xffffffffu, v, o);
    return v;
}

// 16-lane group sum (lanes differing in bits 0..3)
__device__ __forceinline__ float hex_reduce_add(float v) {
    v += __shfl_xor_sync(0xffffffffu, v, 1);
    v += __shfl_xor_sync(0xffffffffu, v, 2);
    v += __shfl_xor_sync(0xffffffffu, v, 4);
    v += __shfl_xor_sync(0xffffffffu, v, 8);
    return v;
}

__device__ __forceinline__ float compute_scale(float cr_cur, float cr_ref) {
    float ratio = cr_ref / (cr_cur + EPSF);
    bool cond = (!isnan(cr_cur)) && (!isnan(cr_ref)) &&
                (fabsf(cr_cur) > EPSF) && (fabsf(cr_ref) > EPSF) &&
                (ratio > EPSF);
    float s = cond ? sqrtf(fabsf(ratio)) : 1.0f;
    if (!isfinite(s)) s = 1.0f;  // 'ok' guard
    return s;
}

// cr over 4 rows in smem, row stride 64 floats
__device__ __forceinline__ float cr_rows(const float* hs, int lane) {
    float sgn = (lane == 31) ? -1.0f : 1.0f;
    float a0 = hs[0 * DD + lane], a1 = hs[0 * DD + lane + 32];
    float b0 = hs[1 * DD + lane], b1 = hs[1 * DD + lane + 32];
    float c0 = hs[2 * DD + lane], c1 = hs[2 * DD + lane + 32];
    float d0 = hs[3 * DD + lane], d1 = hs[3 * DD + lane + 32];
    float hac = warp_reduce_add(a0 * c0 + sgn * a1 * c1);
    float hbd = warp_reduce_add(b0 * d0 + sgn * b1 * d1);
    float had = warp_reduce_add(a0 * d0 + sgn * a1 * d1);
    float hbc = warp_reduce_add(b0 * c0 + sgn * b1 * c1);
    return (hac * hbd) / (had * hbc + EPSF);
}

// --------------------------------------------------------------------------
// Single-pass fixed-capacity CSR fill; 4 edges per thread via int4 loads.
// --------------------------------------------------------------------------
__global__ void fill_kernel(const int4* __restrict__ src4,
                            const int4* __restrict__ dst4) {
    int t = blockIdx.x * blockDim.x + threadIdx.x;
    if (t >= EE / 4) return;
    int4 s = __ldg(&src4[t]);
    int4 d = __ldg(&dst4[t]);
#pragma unroll
    for (int j = 0; j < 4; j++) {
        int dd = (&d.x)[j];
        int ss = (&s.x)[j];
        int p = atomicAdd(&g_cur[dd], 1);
        if (p < CAP) g_csr[dd * CAP + p] = ss;
    }
}

// --------------------------------------------------------------------------
// Shared inner product: 8 rows x 4 cols per thread, k-chunk 2, FFMA2.
// (used by gemm0: 128-row blocks)
// --------------------------------------------------------------------------
__device__ __forceinline__ void mm_8x4(const float (*xs)[64],
                                       const float (*ws)[64],
                                       int ty, int tx,
                                       unsigned long long accp[8][2]) {
#pragma unroll
    for (int i = 0; i < 8; i++) { accp[i][0] = 0ull; accp[i][1] = 0ull; }
#pragma unroll
    for (int k0 = 0; k0 < 64; k0 += 2) {
        float2 xv[8];
#pragma unroll
        for (int i = 0; i < 8; i++)
            xv[i] = *(const float2*)&xs[ty * 8 + i][k0];
#pragma unroll
        for (int kk = 0; kk < 2; kk++) {
            ulonglong2 w2 = *(const ulonglong2*)&ws[k0 + kk][tx * 4];
#pragma unroll
            for (int i = 0; i < 8; i++) {
                unsigned xb = __float_as_uint(kk ? xv[i].y : xv[i].x);
                unsigned long long x2;
                PACK_F32X2(x2, xb, xb);
                FMA_F32X2(accp[i][0], x2, w2.x, accp[i][0]);
                FMA_F32X2(accp[i][1], x2, w2.y, accp[i][1]);
            }
        }
    }
}

// --------------------------------------------------------------------------
// 4 rows x 4 cols per thread over 64-row tile (round-5 proven shape).
// --------------------------------------------------------------------------
__device__ __forceinline__ void mm_4x4(const float (*xs)[64],
                                       const float (*ws)[64],
                                       int ty, int tx,
                                       unsigned long long accp[4][2]) {
#pragma unroll
    for (int i = 0; i < 4; i++) { accp[i][0] = 0ull; accp[i][1] = 0ull; }
#pragma unroll
    for (int k0 = 0; k0 < 64; k0 += 4) {
        float4 xv4[4];
#pragma unroll
        for (int i = 0; i < 4; i++)
            xv4[i] = *(const float4*)&xs[ty * 4 + i][k0];
#pragma unroll
        for (int kk = 0; kk < 4; kk++) {
            ulonglong2 w2 = *(const ulonglong2*)&ws[k0 + kk][tx * 4];
#pragma unroll
            for (int i = 0; i < 4; i++) {
                unsigned xb = __float_as_uint((&xv4[i].x)[kk]);
                unsigned long long x2;
                PACK_F32X2(x2, xb, xb);
                FMA_F32X2(accp[i][0], x2, w2.x, accp[i][0]);
                FMA_F32X2(accp[i][1], x2, w2.y, accp[i][1]);
            }
        }
    }
}

// --------------------------------------------------------------------------
// gemm0: g_h0h = half(normalize(X @ W0 + b0)); block 0 stores cr_init & cr0.
// 128 rows x 64 cols per block, 256 threads, 8x4 micro-tile.
// --------------------------------------------------------------------------
__global__ void __launch_bounds__(256, 3)
gemm0_kernel(const float* __restrict__ Xin, const float* __restrict__ W,
             const float* __restrict__ B) {
    extern __shared__ float smdyn[];
    float (*ws)[64] = (float(*)[64])smdyn;               // 64x64 (16KB)
    float (*xs)[64] = (float(*)[64])(smdyn + 4096);      // 128x64 (32KB)
    float (*crbuf)[64] = (float(*)[64])(smdyn + 12288);  // 4x64 (1KB)

    int tid = threadIdx.x;
    int rbase = blockIdx.x * 128;

#pragma unroll
    for (int i = 0; i < 4; i++) {
        int idx = tid + i * 256;
        ((float4*)ws)[idx] = ((const float4*)W)[idx];
    }
#pragma unroll
    for (int i = 0; i < 8; i++) {
        int idx = tid + i * 256;
        int rr = idx >> 4, kk = (idx & 15) * 4;
        int gr = rbase + rr;
        float4 v = make_float4(0.f, 0.f, 0.f, 0.f);
        if (gr < NN) v = *(const float4*)&Xin[gr * DD + kk];
        *(float4*)&xs[rr][kk] = v;
    }
    __syncthreads();

    int ty = tid >> 4;
    int tx = tid & 15;

    unsigned long long accp[8][2];
    mm_8x4(xs, ws, ty, tx, accp);

    float4 b4 = *(const float4*)&B[tx * 4];
#pragma unroll
    for (int i = 0; i < 8; i++) {
        int gr = rbase + ty * 8 + i;
        unsigned a0u, a1u, a2u, a3u;
        UNPACK_F32X2(a0u, a1u, accp[i][0]);
        UNPACK_F32X2(a2u, a3u, accp[i][1]);
        float v0 = __uint_as_float(a0u) + b4.x;
        float v1 = __uint_as_float(a1u) + b4.y;
        float v2 = __uint_as_float(a2u) + b4.z;
        float v3 = __uint_as_float(a3u) + b4.w;
        float ss = v0 * v0 + v1 * v1 + v2 * v2 + v3 * v3;
        ss = hex_reduce_add(ss);
        float inv = 1.f / (sqrtf(ss) + EPSF);
        v0 *= inv; v1 *= inv; v2 *= inv; v3 *= inv;
        if (gr < NN) {
            __half2 p01 = __floats2half2_rn(v0, v1);
            __half2 p23 = __floats2half2_rn(v2, v3);
            uint2 st;
            st.x = *(unsigned*)&p01;
            st.y = *(unsigned*)&p23;
            *(uint2*)&g_h0h[gr * DD + tx * 4] = st;
        }
        if (blockIdx.x == 0 && ty == 0 && i < 4) {
            crbuf[i][tx * 4 + 0] = v0;
            crbuf[i][tx * 4 + 1] = v1;
            crbuf[i][tx * 4 + 2] = v2;
            crbuf[i][tx * 4 + 3] = v3;
        }
    }

    if (blockIdx.x == 0) {
        __syncthreads();
        if (tid < 32) {
            float cr = cr_rows(&crbuf[0][0], tid);
            if (tid == 0) g_scalars[3] = cr;   // cr0 (of h0)
        } else if (tid < 64) {
            float cr = cr_rows(&xs[0][0], tid - 32);
            if (tid == 32) g_scalars[0] = cr;  // cr_init (of x)
        }
    }
}

// --------------------------------------------------------------------------
// Fused gemm12 (round-5 shape: 64 rows/block, 256 threads, 4x4 micro):
//   agg = fp16 CSR gather-sum of g_h0h  -> xs
//   hm  = normalize((agg @ Wm)/deg + bm) -> xs (via regs)
//   out = sf * relu(normalize(sm*(hm @ W1) + b1))
// int4 CSR index loads; launch_bounds(256,4) for 4 blocks/SM.
// --------------------------------------------------------------------------
__global__ void __launch_bounds__(256, 4)
gemm12_kernel(const float* __restrict__ Wm, const float* __restrict__ bm,
              const float* __restrict__ W1, const float* __restrict__ b1,
              float* __restrict__ Yout) {
    __shared__ __align__(16) float wsm[64][64];   // 16KB
    __shared__ __align__(16) float ws1[64][64];   // 16KB
    __shared__ __align__(16) float xs[64][64];    // 16KB

    int tid = threadIdx.x;
    int rbase = blockIdx.x * 64;

#pragma unroll
    for (int i = 0; i < 4; i++) {
        int idx = tid + i * 256;
        ((float4*)wsm)[idx] = ((const float4*)Wm)[idx];
        ((float4*)ws1)[idx] = ((const float4*)W1)[idx];
    }

    // Fused fp16 gather: 32 groups of 8 threads; group handles rows
    // grp*2 + it; thread q loads 16B (8 halfs) of the 128B row.
    {
        int grp = tid >> 3;
        int q = tid & 7;
#pragma unroll
        for (int it = 0; it < 2; it++) {
            int rr = grp * 2 + it;
            int n = rbase + rr;
            float a[8];
#pragma unroll
            for (int j = 0; j < 8; j++) a[j] = 0.f;
            if (n < NN) {
                int dg = min(g_cur[n], CAP);
                const int4* lst4 = (const int4*)&g_csr[n * CAP];
                const __half* tb = g_h0h;
                int i = 0;
                for (; i + 4 <= dg; i += 4) {
                    int4 s4 = __ldg(&lst4[i >> 2]);
                    uint4 r0 = *(const uint4*)&tb[s4.x * DD + q * 8];
                    uint4 r1 = *(const uint4*)&tb[s4.y * DD + q * 8];
                    uint4 r2 = *(const uint4*)&tb[s4.z * DD + q * 8];
                    uint4 r3 = *(const uint4*)&tb[s4.w * DD + q * 8];
#pragma unroll
                    for (int c = 0; c < 4; c++) {
                        unsigned u0 = (&r0.x)[c], u1 = (&r1.x)[c];
                        unsigned u2 = (&r2.x)[c], u3 = (&r3.x)[c];
                        float2 f0 = __half22float2(*(__half2*)&u0);
                        float2 f1 = __half22float2(*(__half2*)&u1);
                        float2 f2 = __half22float2(*(__half2*)&u2);
                        float2 f3 = __half22float2(*(__half2*)&u3);
                        a[c * 2 + 0] += (f0.x + f1.x) + (f2.x + f3.x);
                        a[c * 2 + 1] += (f0.y + f1.y) + (f2.y + f3.y);
                    }
                }
                for (; i < dg; i++) {
                    int s0 = g_csr[n * CAP + i];
                    uint4 r0 = *(const uint4*)&tb[s0 * DD + q * 8];
#pragma unroll
                    for (int c = 0; c < 4; c++) {
                        unsigned u0 = (&r0.x)[c];
                        float2 f0 = __half22float2(*(__half2*)&u0);
                        a[c * 2 + 0] += f0.x;
                        a[c * 2 + 1] += f0.y;
                    }
                }
            }
            *(float4*)&xs[rr][q * 8 + 0] = make_float4(a[0], a[1], a[2], a[3]);
            *(float4*)&xs[rr][q * 8 + 4] = make_float4(a[4], a[5], a[6], a[7]);
        }
    }
    __syncthreads();

    int ty = tid >> 4;
    int tx = tid & 15;

    // ---- pass 1: agg @ Wm ----
    unsigned long long accp[4][2];
    mm_4x4(xs, wsm, ty, tx, accp);

    // pass-1 epilogue: hm = normalize(acc/deg + bm), repacked into accp
    {
        float4 ba = *(const float4*)&bm[tx * 4];
#pragma unroll
        for (int i = 0; i < 4; i++) {
            int gr = rbase + ty * 4 + i;
            float c = (gr < NN) ? (float)min(g_cur[gr], CAP) : 1.f;
            float rs = 1.f / fmaxf(c, 1.f);
            unsigned a0u, a1u, a2u, a3u;
            UNPACK_F32X2(a0u, a1u, accp[i][0]);
            UNPACK_F32X2(a2u, a3u, accp[i][1]);
            float v0 = fmaf(__uint_as_float(a0u), rs, ba.x);
            float v1 = fmaf(__uint_as_float(a1u), rs, ba.y);
            float v2 = fmaf(__uint_as_float(a2u), rs, ba.z);
            float v3 = fmaf(__uint_as_float(a3u), rs, ba.w);
            float ss = v0 * v0 + v1 * v1 + v2 * v2 + v3 * v3;
            ss = hex_reduce_add(ss);
            float inv = 1.f / (sqrtf(ss) + EPSF);
            PACK_F32X2(accp[i][0], __float_as_uint(v0 * inv),
                       __float_as_uint(v1 * inv));
            PACK_F32X2(accp[i][1], __float_as_uint(v2 * inv),
                       __float_as_uint(v3 * inv));
        }
    }

    __syncthreads();  // everyone done reading xs (agg)
#pragma unroll
    for (int i = 0; i < 4; i++) {
        unsigned l0, h0, l1, h1;
        UNPACK_F32X2(l0, h0, accp[i][0]);
        UNPACK_F32X2(l1, h1, accp[i][1]);
        *(float4*)&xs[ty * 4 + i][tx * 4] =
            make_float4(__uint_as_float(l0), __uint_as_float(h0),
                        __uint_as_float(l1), __uint_as_float(h1));
    }
    __syncthreads();

    // ---- pass 2: hm @ W1 ----
    mm_4x4(xs, ws1, ty, tx, accp);

    float4 b14 = *(const float4*)&b1[tx * 4];
    float sm = g_scalars[1];
    float sf = g_scalars[2];
#pragma unroll
    for (int i = 0; i < 4; i++) {
        int gr = rbase + ty * 4 + i;
        unsigned a0u, a1u, a2u, a3u;
        UNPACK_F32X2(a0u, a1u, accp[i][0]);
        UNPACK_F32X2(a2u, a3u, accp[i][1]);
        float v0 = fmaf(sm, __uint_as_float(a0u), b14.x);
        float v1 = fmaf(sm, __uint_as_float(a1u), b14.y);
        float v2 = fmaf(sm, __uint_as_float(a2u), b14.z);
        float v3 = fmaf(sm, __uint_as_float(a3u), b14.w);
        float ss = v0 * v0 + v1 * v1 + v2 * v2 + v3 * v3;
        ss = hex_reduce_add(ss);
        float inv = 1.f / (sqrtf(ss) + EPSF);
        v0 = fmaxf(v0 * inv, 0.f) * sf;
        v1 = fmaxf(v1 * inv, 0.f) * sf;
        v2 = fmaxf(v2 * inv, 0.f) * sf;
        v3 = fmaxf(v3 * inv, 0.f) * sf;
        if (gr < NN)
            *(float4*)&Yout[gr * DD + tx * 4] = make_float4(v0, v1, v2, v3);
    }
}

// --------------------------------------------------------------------------
// Merged small kernel: rows 0..3 of both remaining layers -> scale_m and
// scale_fin.
// --------------------------------------------------------------------------
__global__ void small4_kernel(const float* __restrict__ Wm,
                              const float* __restrict__ bm,
                              const float* __restrict__ W1,
                              const float* __restrict__ b1) {
    __shared__ float ins[4][DD];
    __shared__ float hs[4][DD];
    __shared__ float red[8];
    __shared__ float s_scale;
    int tid = threadIdx.x;
    int r = tid >> 6, c = tid & 63;

    // phase A: message rows 0..3 -> hm rows, scale_m
    {
        int dg = min(g_cur[r], CAP);
        const int* lst = &g_csr[r * CAP];
        float s = 0.f;
        for (int i = 0; i < dg; i++)
            s += __half2float(g_h0h[lst[i] * DD + c]);
        ins[r][c] = s / fmaxf((float)dg, 1.f);
    }
    __syncthreads();
    float acc = 0.f;
#pragma unroll
    for (int k = 0; k < 64; k++) acc = fmaf(ins[r][k], Wm[k * DD + c], acc);
    acc += bm[c];
    float ss = acc * acc;
#pragma unroll
    for (int o = 16; o; o >>= 1) ss += __shfl_xor_sync(0xffffffffu, ss, o);
    if ((tid & 31) == 0) red[tid >> 5] = ss;
    __syncthreads();
    float tot = red[r * 2] + red[r * 2 + 1];
    float y = acc / (sqrtf(tot) + EPSF);
    hs[r][c] = y;
    __syncthreads();
    if (tid < 32) {
        float cr_cur = cr_rows(&hs[0][0], tid);
        if (tid == 0) {
            float sc = compute_scale(cr_cur, g_scalars[3]);
            g_scalars[1] = sc;
            s_scale = sc;
        }
    }
    __syncthreads();

    // phase B: final rows 0..3 -> scale_fin
    float accB = 0.f;
#pragma unroll
    for (int k = 0; k < 64; k++) accB = fmaf(hs[r][k], W1[k * DD + c], accB);
    accB = fmaf(s_scale, accB, b1[c]);
    float ssB = accB * accB;
#pragma unroll
    for (int o = 16; o; o >>= 1) ssB += __shfl_xor_sync(0xffffffffu, ssB, o);
    if ((tid & 31) == 0) red[tid >> 5] = ssB;
    __syncthreads();
    float totB = red[r * 2] + red[r * 2 + 1];
    float yB = fmaxf(accB / (sqrtf(totB) + EPSF), 0.f);
    ins[r][c] = yB;   // reuse ins
    __syncthreads();
    if (tid < 32) {
        float cr2 = cr_rows(&ins[0][0], tid);
        if (tid == 0)
            g_scalars[2] = compute_scale(cr2, g_scalars[0]);
    }
}

// --------------------------------------------------------------------------
extern "C" void kernel_launch(void* const* d_in, const int* in_sizes, int n_in,
                              void* d_out, int out_size) {
    const float* x  = (const float*)d_in[0];
    const int*  ei  = (const int*)d_in[1];
    const float* W0 = (const float*)d_in[2];
    const float* b0 = (const float*)d_in[3];
    const float* Wm = (const float*)d_in[4];
    const float* bm = (const float*)d_in[5];
    const float* W1 = (const float*)d_in[6];
    const float* b1 = (const float*)d_in[7];
    float* out = (float*)d_out;
    const int4* src4 = (const int4*)ei;
    const int4* dst4 = (const int4*)(ei + EE);

    const int g0blocks = (NN + 127) / 128;   // 782
    const int g12blocks = (NN + 63) / 64;    // 1563
    const int eblocks = (EE / 4 + 255) / 256;
    const int SMEM0 = (4096 + 8192 + 256) * 4;   // 50176

    // one-time host objects (host-side only; identical work every call)
    static cudaStream_t s2 = nullptr;
    static cudaEvent_t evF, evA, evFill, evB;
    static void* curp = nullptr;
    if (!s2) {
        cudaStreamCreateWithFlags(&s2, cudaStreamNonBlocking);
        cudaEventCreateWithFlags(&evF, cudaEventDisableTiming);
        cudaEventCreateWithFlags(&evA, cudaEventDisableTiming);
        cudaEventCreateWithFlags(&evFill, cudaEventDisableTiming);
        cudaEventCreateWithFlags(&evB, cudaEventDisableTiming);
        cudaGetSymbolAddress(&curp, g_cur);
        cudaFuncSetAttribute(gemm0_kernel,
                             cudaFuncAttributeMaxDynamicSharedMemorySize,
                             SMEM0);
    }

    cudaStream_t s0 = 0;  // capture stream

    // fork: gemm0 on s2, concurrent with CSR build on s0
    cudaEventRecord(evF, s0);
    cudaStreamWaitEvent(s2, evF, 0);
    gemm0_kernel<<<g0blocks, 256, SMEM0, s2>>>(x, W0, b0);
    cudaEventRecord(evA, s2);

    // CSR build on s0
    cudaMemsetAsync(curp, 0, NN * sizeof(int), s0);
    fill_kernel<<<eblocks, 256, 0, s0>>>(src4, dst4);
    cudaEventRecord(evFill, s0);

    // small4 on s2 (after gemm0 [stream order] + fill)
    cudaStreamWaitEvent(s2, evFill, 0);
    small4_kernel<<<1, 256, 0, s2>>>(Wm, bm, W1, b1);
    cudaEventRecord(evB, s2);

    // fused gemm1+gemm2 on s0 (after fill [stream order] + gemm0 + small4)
    cudaStreamWaitEvent(s0, evA, 0);
    cudaStreamWaitEvent(s0, evB, 0);
    gemm12_kernel<<<g12blocks, 256, 0, s0>>>(Wm, bm, W1, b1, out);
}

// round 9
// speedup vs baseline: 1.4797x; 1.1161x over previous
#include <cuda_runtime.h>
#include <cuda_fp16.h>
#include <cstdint>
#include <math.h>

#define NN 100000
#define DD 64
#define EE 1600000
#define EPSF 1e-8f
#define CAP 64   // fixed CSR capacity per node (deg ~ Poisson(16); P(>64)~1e-19)

#define WS_STRIDE 72   // W smem row stride (bank = 8*tid4+grp, conflict-free)
#define XS_STRIDE 68   // X smem row stride (bank = 4*grp+tid4, conflict-free)

// Scratch (static device globals — no allocation)
__device__ __align__(16) __half g_h0h[NN * DD];   // h0 in fp16 (gather table)
__device__ int g_cur[NN];                         // slot cursor == degree
__device__ __align__(16) int g_csr[NN * CAP];
// [0]=cr_init, [1]=scale_m, [2]=scale_fin, [3]=cr0
__device__ float g_scalars[4];

// ---- packed f32x2 helpers (FFMA2, used by gemm0) ----
#define FMA_F32X2(d, a, b, c) \
    asm("fma.rn.f32x2 %0, %1, %2, %3;" : "=l"(d) : "l"(a), "l"(b), "l"(c))
#define PACK_F32X2(out, lo, hi) \
    asm("mov.b64 %0, {%1, %2};" : "=l"(out) : "r"(lo), "r"(hi))
#define UNPACK_F32X2(lo, hi, in) \
    asm("mov.b64 {%0, %1}, %2;" : "=r"(lo), "=r"(hi) : "l"(in))

// ---- tf32 mma helpers ----
__device__ __forceinline__ float to_tf32(float f) {
    unsigned u;
    asm("cvt.rna.tf32.f32 %0, %1;" : "=r"(u) : "f"(f));
    return __uint_as_float(u);
}

__device__ __forceinline__ void mma_tf32(float* d, const unsigned* a,
                                         const unsigned* b) {
    asm volatile(
        "mma.sync.aligned.m16n8k8.row.col.f32.tf32.tf32.f32 "
        "{%0,%1,%2,%3}, {%4,%5,%6,%7}, {%8,%9}, {%0,%1,%2,%3};\n"
        : "+f"(d[0]), "+f"(d[1]), "+f"(d[2]), "+f"(d[3])
        : "r"(a[0]), "r"(a[1]), "r"(a[2]), "r"(a[3]),
          "r"(b[0]), "r"(b[1]));
}

__device__ __forceinline__ float warp_reduce_add(float v) {
#pragma unroll
    for (int o = 16; o; o >>= 1) v += __shfl_xor_sync(0xffffffffu, v, o);
    return v;
}

// 16-lane group sum (lanes differing in bits 0..3)
__device__ __forceinline__ float hex_reduce_add(float v) {
    v += __shfl_xor_sync(0xffffffffu, v, 1);
    v += __shfl_xor_sync(0xffffffffu, v, 2);
    v += __shfl_xor_sync(0xffffffffu, v, 4);
    v += __shfl_xor_sync(0xffffffffu, v, 8);
    return v;
}

// 4-lane quad sum (lanes differing in bits 0..1)
__device__ __forceinline__ float quad_reduce_add(float v) {
    v += __shfl_xor_sync(0xffffffffu, v, 1);
    v += __shfl_xor_sync(0xffffffffu, v, 2);
    return v;
}

__device__ __forceinline__ float compute_scale(float cr_cur, float cr_ref) {
    float ratio = cr_ref / (cr_cur + EPSF);
    bool cond = (!isnan(cr_cur)) && (!isnan(cr_ref)) &&
                (fabsf(cr_cur) > EPSF) && (fabsf(cr_ref) > EPSF) &&
                (ratio > EPSF);
    float s = cond ? sqrtf(fabsf(ratio)) : 1.0f;
    if (!isfinite(s)) s = 1.0f;  // 'ok' guard
    return s;
}

// cr over 4 rows in smem, row stride 64 floats
__device__ __forceinline__ float cr_rows(const float* hs, int lane) {
    float sgn = (lane == 31) ? -1.0f : 1.0f;
    float a0 = hs[0 * DD + lane], a1 = hs[0 * DD + lane + 32];
    float b0 = hs[1 * DD + lane], b1 = hs[1 * DD + lane + 32];
    float c0 = hs[2 * DD + lane], c1 = hs[2 * DD + lane + 32];
    float d0 = hs[3 * DD + lane], d1 = hs[3 * DD + lane + 32];
    float hac = warp_reduce_add(a0 * c0 + sgn * a1 * c1);
    float hbd = warp_reduce_add(b0 * d0 + sgn * b1 * d1);
    float had = warp_reduce_add(a0 * d0 + sgn * a1 * d1);
    float hbc = warp_reduce_add(b0 * c0 + sgn * b1 * c1);
    return (hac * hbd) / (had * hbc + EPSF);
}

// --------------------------------------------------------------------------
// Single-pass fixed-capacity CSR fill; 4 edges per thread via int4 loads.
// --------------------------------------------------------------------------
__global__ void fill_kernel(const int4* __restrict__ src4,
                            const int4* __restrict__ dst4) {
    int t = blockIdx.x * blockDim.x + threadIdx.x;
    if (t >= EE / 4) return;
    int4 s = __ldg(&src4[t]);
    int4 d = __ldg(&dst4[t]);
#pragma unroll
    for (int j = 0; j < 4; j++) {
        int dd = (&d.x)[j];
        int ss = (&s.x)[j];
        int p = atomicAdd(&g_cur[dd], 1);
        if (p < CAP) g_csr[dd * CAP + p] = ss;
    }
}

// --------------------------------------------------------------------------
// 8 rows x 4 cols per thread, k-chunk 2, FFMA2 (gemm0 path, stride-64 smem)
// --------------------------------------------------------------------------
__device__ __forceinline__ void mm_8x4(const float (*xs)[64],
                                       const float (*ws)[64],
                                       int ty, int tx,
                                       unsigned long long accp[8][2]) {
#pragma unroll
    for (int i = 0; i < 8; i++) { accp[i][0] = 0ull; accp[i][1] = 0ull; }
#pragma unroll
    for (int k0 = 0; k0 < 64; k0 += 2) {
        float2 xv[8];
#pragma unroll
        for (int i = 0; i < 8; i++)
            xv[i] = *(const float2*)&xs[ty * 8 + i][k0];
#pragma unroll
        for (int kk = 0; kk < 2; kk++) {
            ulonglong2 w2 = *(const ulonglong2*)&ws[k0 + kk][tx * 4];
#pragma unroll
            for (int i = 0; i < 8; i++) {
                unsigned xb = __float_as_uint(kk ? xv[i].y : xv[i].x);
                unsigned long long x2;
                PACK_F32X2(x2, xb, xb);
                FMA_F32X2(accp[i][0], x2, w2.x, accp[i][0]);
                FMA_F32X2(accp[i][1], x2, w2.y, accp[i][1]);
            }
        }
    }
}

// --------------------------------------------------------------------------
// gemm0: g_h0h = half(normalize(X @ W0 + b0)); block 0 stores cr_init & cr0.
// 128 rows x 64 cols per block, 256 threads, 8x4 micro-tile, FFMA2.
// --------------------------------------------------------------------------
__global__ void __launch_bounds__(256, 3)
gemm0_kernel(const float* __restrict__ Xin, const float* __restrict__ W,
             const float* __restrict__ B) {
    extern __shared__ float smdyn[];
    float (*ws)[64] = (float(*)[64])smdyn;               // 64x64 (16KB)
    float (*xs)[64] = (float(*)[64])(smdyn + 4096);      // 128x64 (32KB)
    float (*crbuf)[64] = (float(*)[64])(smdyn + 12288);  // 4x64 (1KB)

    int tid = threadIdx.x;
    int rbase = blockIdx.x * 128;

#pragma unroll
    for (int i = 0; i < 4; i++) {
        int idx = tid + i * 256;
        ((float4*)ws)[idx] = ((const float4*)W)[idx];
    }
#pragma unroll
    for (int i = 0; i < 8; i++) {
        int idx = tid + i * 256;
        int rr = idx >> 4, kk = (idx & 15) * 4;
        int gr = rbase + rr;
        float4 v = make_float4(0.f, 0.f, 0.f, 0.f);
        if (gr < NN) v = *(const float4*)&Xin[gr * DD + kk];
        *(float4*)&xs[rr][kk] = v;
    }
    __syncthreads();

    int ty = tid >> 4;
    int tx = tid & 15;

    unsigned long long accp[8][2];
    mm_8x4(xs, ws, ty, tx, accp);

    float4 b4 = *(const float4*)&B[tx * 4];
#pragma unroll
    for (int i = 0; i < 8; i++) {
        int gr = rbase + ty * 8 + i;
        unsigned a0u, a1u, a2u, a3u;
        UNPACK_F32X2(a0u, a1u, accp[i][0]);
        UNPACK_F32X2(a2u, a3u, accp[i][1]);
        float v0 = __uint_as_float(a0u) + b4.x;
        float v1 = __uint_as_float(a1u) + b4.y;
        float v2 = __uint_as_float(a2u) + b4.z;
        float v3 = __uint_as_float(a3u) + b4.w;
        float ss = v0 * v0 + v1 * v1 + v2 * v2 + v3 * v3;
        ss = hex_reduce_add(ss);
        float inv = 1.f / (sqrtf(ss) + EPSF);
        v0 *= inv; v1 *= inv; v2 *= inv; v3 *= inv;
        if (gr < NN) {
            __half2 p01 = __floats2half2_rn(v0, v1);
            __half2 p23 = __floats2half2_rn(v2, v3);
            uint2 st;
            st.x = *(unsigned*)&p01;
            st.y = *(unsigned*)&p23;
            *(uint2*)&g_h0h[gr * DD + tx * 4] = st;
        }
        if (blockIdx.x == 0 && ty == 0 && i < 4) {
            crbuf[i][tx * 4 + 0] = v0;
            crbuf[i][tx * 4 + 1] = v1;
            crbuf[i][tx * 4 + 2] = v2;
            crbuf[i][tx * 4 + 3] = v3;
        }
    }

    if (blockIdx.x == 0) {
        __syncthreads();
        if (tid < 32) {
            float cr = cr_rows(&crbuf[0][0], tid);
            if (tid == 0) g_scalars[3] = cr;   // cr0 (of h0)
        } else if (tid < 64) {
            float cr = cr_rows(&xs[0][0], tid - 32);
            if (tid == 32) g_scalars[0] = cr;  // cr_init (of x)
        }
    }
}

// --------------------------------------------------------------------------
// Fused gemm12 with tf32 tensor-core MMA.
// 128 rows x 64 cols per block, 256 threads (8 warps). Warp w owns the
// 16-row strip [w*16, w*16+16); both passes are warp-private in rows, so
// only ONE __syncthreads (after gather) is needed.
//   agg = fp16 CSR gather-sum of g_h0h  -> xs (tf32-rounded)
//   hm  = normalize((agg @ Wm)/deg + bm) -> xs (tf32-rounded)
//   out = sf * relu(normalize(sm*(hm @ W1) + b1))
// --------------------------------------------------------------------------
__global__ void __launch_bounds__(256, 3)
gemm12_kernel(const float* __restrict__ Wm, const float* __restrict__ bm,
              const float* __restrict__ W1, const float* __restrict__ b1,
              float* __restrict__ Yout) {
    extern __shared__ float smdyn[];
    float* wsm = smdyn;                       // [64][WS_STRIDE]
    float* ws1 = smdyn + 64 * WS_STRIDE;      // [64][WS_STRIDE]
    float* xs  = smdyn + 128 * WS_STRIDE;     // [128][XS_STRIDE]

    int tid = threadIdx.x;
    int rbase = blockIdx.x * 128;

    // W tiles (tf32-rounded at store)
#pragma unroll
    for (int i = 0; i < 4; i++) {
        int e4 = tid + i * 256;          // float4 index into 64x64
        float4 wm4 = ((const float4*)Wm)[e4];
        float4 w14 = ((const float4*)W1)[e4];
        int k = (e4 * 4) >> 6, n = (e4 * 4) & 63;
        float4 a = make_float4(to_tf32(wm4.x), to_tf32(wm4.y),
                               to_tf32(wm4.z), to_tf32(wm4.w));
        float4 b = make_float4(to_tf32(w14.x), to_tf32(w14.y),
                               to_tf32(w14.z), to_tf32(w14.w));
        *(float4*)&wsm[k * WS_STRIDE + n] = a;
        *(float4*)&ws1[k * WS_STRIDE + n] = b;
    }

    // Fused fp16 gather: 32 groups of 8 threads; group handles row
    // it*32+grp; thread q covers 16B (8 halfs) of the 128B row.
    {
        int grp = tid >> 3;
        int q = tid & 7;
#pragma unroll
        for (int it = 0; it < 4; it++) {
            int rr = it * 32 + grp;
            int n = rbase + rr;
            float a[8];
#pragma unroll
            for (int j = 0; j < 8; j++) a[j] = 0.f;
            if (n < NN) {
                int dg = min(g_cur[n], CAP);
                const int4* lst4 = (const int4*)&g_csr[n * CAP];
                const __half* tb = g_h0h;
                int i = 0;
                for (; i + 4 <= dg; i += 4) {
                    int4 s4 = __ldg(&lst4[i >> 2]);
                    uint4 r0 = *(const uint4*)&tb[s4.x * DD + q * 8];
                    uint4 r1 = *(const uint4*)&tb[s4.y * DD + q * 8];
                    uint4 r2 = *(const uint4*)&tb[s4.z * DD + q * 8];
                    uint4 r3 = *(const uint4*)&tb[s4.w * DD + q * 8];
#pragma unroll
                    for (int c = 0; c < 4; c++) {
                        unsigned u0 = (&r0.x)[c], u1 = (&r1.x)[c];
                        unsigned u2 = (&r2.x)[c], u3 = (&r3.x)[c];
                        float2 f0 = __half22float2(*(__half2*)&u0);
                        float2 f1 = __half22float2(*(__half2*)&u1);
                        float2 f2 = __half22float2(*(__half2*)&u2);
                        float2 f3 = __half22float2(*(__half2*)&u3);
                        a[c * 2 + 0] += (f0.x + f1.x) + (f2.x + f3.x);
                        a[c * 2 + 1] += (f0.y + f1.y) + (f2.y + f3.y);
                    }
                }
                for (; i < dg; i++) {
                    int s0 = g_csr[n * CAP + i];
                    uint4 r0 = *(const uint4*)&tb[s0 * DD + q * 8];
#pragma unroll
                    for (int c = 0; c < 4; c++) {
                        unsigned u0 = (&r0.x)[c];
                        float2 f0 = __half22float2(*(__half2*)&u0);
                        a[c * 2 + 0] += f0.x;
                        a[c * 2 + 1] += f0.y;
                    }
                }
            }
#pragma unroll
            for (int j = 0; j < 8; j++) a[j] = to_tf32(a[j]);
            *(float4*)&xs[rr * XS_STRIDE + q * 8 + 0] =
                make_float4(a[0], a[1], a[2], a[3]);
            *(float4*)&xs[rr * XS_STRIDE + q * 8 + 4] =
                make_float4(a[4], a[5], a[6], a[7]);
        }
    }
    __syncthreads();   // only barrier: rows become warp-private from here

    int warp = tid >> 5;
    int lane = tid & 31;
    int grp = lane >> 2;    // 0..7
    int tid4 = lane & 3;    // 0..3
    int mrow = warp * 16;   // warp's row strip base (local)

    float d[8][4];

    // ---- pass 1: agg @ Wm ----
#pragma unroll
    for (int nt = 0; nt < 8; nt++)
#pragma unroll
        for (int j = 0; j < 4; j++) d[nt][j] = 0.f;
#pragma unroll
    for (int ks = 0; ks < 8; ks++) {
        unsigned a[4];
        const float* xr0 = xs + (mrow + grp) * XS_STRIDE + ks * 8 + tid4;
        const float* xr1 = xr0 + 8 * XS_STRIDE;
        a[0] = __float_as_uint(xr0[0]);
        a[1] = __float_as_uint(xr1[0]);
        a[2] = __float_as_uint(xr0[4]);
        a[3] = __float_as_uint(xr1[4]);
#pragma unroll
        for (int nt = 0; nt < 8; nt++) {
            unsigned b[2];
            const float* wr = wsm + (ks * 8 + tid4) * WS_STRIDE + nt * 8 + grp;
            b[0] = __float_as_uint(wr[0]);
            b[1] = __float_as_uint(wr[4 * WS_STRIDE]);
            mma_tf32(d[nt], a, b);
        }
    }

    // pass-1 epilogue: hm = normalize(acc/deg + bm) -> xs (tf32)
    {
        int gr0 = rbase + mrow + grp;
        int gr1 = gr0 + 8;
        float c0 = (gr0 < NN) ? (float)min(g_cur[gr0], CAP) : 1.f;
        float c1 = (gr1 < NN) ? (float)min(g_cur[gr1], CAP) : 1.f;
        float rs0 = 1.f / fmaxf(c0, 1.f);
        float rs1 = 1.f / fmaxf(c1, 1.f);
        float ss0 = 0.f, ss1 = 0.f;
#pragma unroll
        for (int nt = 0; nt < 8; nt++) {
            float bb0 = __ldg(&bm[nt * 8 + tid4 * 2 + 0]);
            float bb1 = __ldg(&bm[nt * 8 + tid4 * 2 + 1]);
            d[nt][0] = fmaf(d[nt][0], rs0, bb0);
            d[nt][1] = fmaf(d[nt][1], rs0, bb1);
            d[nt][2] = fmaf(d[nt][2], rs1, bb0);
            d[nt][3] = fmaf(d[nt][3], rs1, bb1);
            ss0 += d[nt][0] * d[nt][0] + d[nt][1] * d[nt][1];
            ss1 += d[nt][2] * d[nt][2] + d[nt][3] * d[nt][3];
        }
        ss0 = quad_reduce_add(ss0);
        ss1 = quad_reduce_add(ss1);
        float inv0 = 1.f / (sqrtf(ss0) + EPSF);
        float inv1 = 1.f / (sqrtf(ss1) + EPSF);
#pragma unroll
        for (int nt = 0; nt < 8; nt++) {
            float2 lo = make_float2(to_tf32(d[nt][0] * inv0),
                                    to_tf32(d[nt][1] * inv0));
            float2 hi = make_float2(to_tf32(d[nt][2] * inv1),
                                    to_tf32(d[nt][3] * inv1));
            *(float2*)&xs[(mrow + grp) * XS_STRIDE + nt * 8 + tid4 * 2] = lo;
            *(float2*)&xs[(mrow + grp + 8) * XS_STRIDE + nt * 8 + tid4 * 2] = hi;
        }
    }
    // no barrier needed: each warp reads back only its own rows

    // ---- pass 2: hm @ W1 ----
#pragma unroll
    for (int nt = 0; nt < 8; nt++)
#pragma unroll
        for (int j = 0; j < 4; j++) d[nt][j] = 0.f;
#pragma unroll
    for (int ks = 0; ks < 8; ks++) {
        unsigned a[4];
        const float* xr0 = xs + (mrow + grp) * XS_STRIDE + ks * 8 + tid4;
        const float* xr1 = xr0 + 8 * XS_STRIDE;
        a[0] = __float_as_uint(xr0[0]);
        a[1] = __float_as_uint(xr1[0]);
        a[2] = __float_as_uint(xr0[4]);
        a[3] = __float_as_uint(xr1[4]);
#pragma unroll
        for (int nt = 0; nt < 8; nt++) {
            unsigned b[2];
            const float* wr = ws1 + (ks * 8 + tid4) * WS_STRIDE + nt * 8 + grp;
            b[0] = __float_as_uint(wr[0]);
            b[1] = __float_as_uint(wr[4 * WS_STRIDE]);
            mma_tf32(d[nt], a, b);
        }
    }

    // pass-2 epilogue: out = sf * relu(normalize(sm*acc + b1))
    {
        float sm = g_scalars[1];
        float sf = g_scalars[2];
        int gr0 = rbase + mrow + grp;
        int gr1 = gr0 + 8;
        float ss0 = 0.f, ss1 = 0.f;
#pragma unroll
        for (int nt = 0; nt < 8; nt++) {
            float bb0 = __ldg(&b1[nt * 8 + tid4 * 2 + 0]);
            float bb1 = __ldg(&b1[nt * 8 + tid4 * 2 + 1]);
            d[nt][0] = fmaf(sm, d[nt][0], bb0);
            d[nt][1] = fmaf(sm, d[nt][1], bb1);
            d[nt][2] = fmaf(sm, d[nt][2], bb0);
            d[nt][3] = fmaf(sm, d[nt][3], bb1);
            ss0 += d[nt][0] * d[nt][0] + d[nt][1] * d[nt][1];
            ss1 += d[nt][2] * d[nt][2] + d[nt][3] * d[nt][3];
        }
        ss0 = quad_reduce_add(ss0);
        ss1 = quad_reduce_add(ss1);
        float inv0 = sf / (sqrtf(ss0) + EPSF);
        float inv1 = sf / (sqrtf(ss1) + EPSF);
#pragma unroll
        for (int nt = 0; nt < 8; nt++) {
            if (gr0 < NN) {
                float2 lo = make_float2(fmaxf(d[nt][0], 0.f) * inv0,
                                        fmaxf(d[nt][1], 0.f) * inv0);
                *(float2*)&Yout[gr0 * DD + nt * 8 + tid4 * 2] = lo;
            }
            if (gr1 < NN) {
                float2 hi = make_float2(fmaxf(d[nt][2], 0.f) * inv1,
                                        fmaxf(d[nt][3], 0.f) * inv1);
                *(float2*)&Yout[gr1 * DD + nt * 8 + tid4 * 2] = hi;
            }
        }
    }
}

// --------------------------------------------------------------------------
// Merged small kernel: rows 0..3 of both remaining layers -> scale_m and
// scale_fin. fp32 (more accurate than the main path; scales are ratios).
// --------------------------------------------------------------------------
__global__ void small4_kernel(const float* __restrict__ Wm,
                              const float* __restrict__ bm,
                              const float* __restrict__ W1,
                              const float* __restrict__ b1) {
    __shared__ float ins[4][DD];
    __shared__ float hs[4][DD];
    __shared__ float red[8];
    __shared__ float s_scale;
    int tid = threadIdx.x;
    int r = tid >> 6, c = tid & 63;

    // phase A: message rows 0..3 -> hm rows, scale_m
    {
        int dg = min(g_cur[r], CAP);
        const int* lst = &g_csr[r * CAP];
        float s = 0.f;
        for (int i = 0; i < dg; i++)
            s += __half2float(g_h0h[lst[i] * DD + c]);
        ins[r][c] = s / fmaxf((float)dg, 1.f);
    }
    __syncthreads();
    float acc = 0.f;
#pragma unroll
    for (int k = 0; k < 64; k++) acc = fmaf(ins[r][k], Wm[k * DD + c], acc);
    acc += bm[c];
    float ss = acc * acc;
#pragma unroll
    for (int o = 16; o; o >>= 1) ss += __shfl_xor_sync(0xffffffffu, ss, o);
    if ((tid & 31) == 0) red[tid >> 5] = ss;
    __syncthreads();
    float tot = red[r * 2] + red[r * 2 + 1];
    float y = acc / (sqrtf(tot) + EPSF);
    hs[r][c] = y;
    __syncthreads();
    if (tid < 32) {
        float cr_cur = cr_rows(&hs[0][0], tid);
        if (tid == 0) {
            float sc = compute_scale(cr_cur, g_scalars[3]);
            g_scalars[1] = sc;
            s_scale = sc;
        }
    }
    __syncthreads();

    // phase B: final rows 0..3 -> scale_fin
    float accB = 0.f;
#pragma unroll
    for (int k = 0; k < 64; k++) accB = fmaf(hs[r][k], W1[k * DD + c], accB);
    accB = fmaf(s_scale, accB, b1[c]);
    float ssB = accB * accB;
#pragma unroll
    for (int o = 16; o; o >>= 1) ssB += __shfl_xor_sync(0xffffffffu, ssB, o);
    if ((tid & 31) == 0) red[tid >> 5] = ssB;
    __syncthreads();
    float totB = red[r * 2] + red[r * 2 + 1];
    float yB = fmaxf(accB / (sqrtf(totB) + EPSF), 0.f);
    ins[r][c] = yB;   // reuse ins
    __syncthreads();
    if (tid < 32) {
        float cr2 = cr_rows(&ins[0][0], tid);
        if (tid == 0)
            g_scalars[2] = compute_scale(cr2, g_scalars[0]);
    }
}

// --------------------------------------------------------------------------
extern "C" void kernel_launch(void* const* d_in, const int* in_sizes, int n_in,
                              void* d_out, int out_size) {
    const float* x  = (const float*)d_in[0];
    const int*  ei  = (const int*)d_in[1];
    const float* W0 = (const float*)d_in[2];
    const float* b0 = (const float*)d_in[3];
    const float* Wm = (const float*)d_in[4];
    const float* bm = (const float*)d_in[5];
    const float* W1 = (const float*)d_in[6];
    const float* b1 = (const float*)d_in[7];
    float* out = (float*)d_out;
    const int4* src4 = (const int4*)ei;
    const int4* dst4 = (const int4*)(ei + EE);

    const int g0blocks = (NN + 127) / 128;   // 782
    const int g12blocks = (NN + 127) / 128;  // 782
    const int eblocks = (EE / 4 + 255) / 256;
    const int SMEM0 = (4096 + 8192 + 256) * 4;                    // 50176
    const int SMEM12 = (128 * WS_STRIDE + 128 * XS_STRIDE) * 4;   // 71680

    // one-time host objects (host-side only; identical work every call)
    static cudaStream_t s2 = nullptr;
    static cudaEvent_t evF, evA, evFill, evB;
    static void* curp = nullptr;
    if (!s2) {
        cudaStreamCreateWithFlags(&s2, cudaStreamNonBlocking);
        cudaEventCreateWithFlags(&evF, cudaEventDisableTiming);
        cudaEventCreateWithFlags(&evA, cudaEventDisableTiming);
        cudaEventCreateWithFlags(&evFill, cudaEventDisableTiming);
        cudaEventCreateWithFlags(&evB, cudaEventDisableTiming);
        cudaGetSymbolAddress(&curp, g_cur);
        cudaFuncSetAttribute(gemm0_kernel,
                             cudaFuncAttributeMaxDynamicSharedMemorySize,
                             SMEM0);
        cudaFuncSetAttribute(gemm12_kernel,
                             cudaFuncAttributeMaxDynamicSharedMemorySize,
                             SMEM12);
    }

    cudaStream_t s0 = 0;  // capture stream

    // fork: gemm0 on s2, concurrent with CSR build on s0
    cudaEventRecord(evF, s0);
    cudaStreamWaitEvent(s2, evF, 0);
    gemm0_kernel<<<g0blocks, 256, SMEM0, s2>>>(x, W0, b0);
    cudaEventRecord(evA, s2);

    // CSR build on s0
    cudaMemsetAsync(curp, 0, NN * sizeof(int), s0);
    fill_kernel<<<eblocks, 256, 0, s0>>>(src4, dst4);
    cudaEventRecord(evFill, s0);

    // small4 on s2 (after gemm0 [stream order] + fill)
    cudaStreamWaitEvent(s2, evFill, 0);
    small4_kernel<<<1, 256, 0, s2>>>(Wm, bm, W1, b1);
    cudaEventRecord(evB, s2);

    // fused tensor-core gemm12 on s0 (after fill + gemm0 + small4)
    cudaStreamWaitEvent(s0, evA, 0);
    cudaStreamWaitEvent(s0, evB, 0);
    gemm12_kernel<<<g12blocks, 256, SMEM12, s0>>>(Wm, bm, W1, b1, out);
}

// round 10
// speedup vs baseline: 1.7280x; 1.1679x over previous
#include <cuda_runtime.h>
#include <cuda_fp16.h>
#include <cstdint>
#include <math.h>

#define NN 100000
#define DD 64
#define EE 1600000
#define EPSF 1e-8f
#define CAP 64   // fixed CSR capacity per node (deg ~ Poisson(16); P(>64)~1e-19)

#define WS_STRIDE 72   // W smem row stride (bank = 8*tid4+grp, conflict-free)
#define XS_STRIDE 68   // X smem row stride (bank = 4*grp+tid4, conflict-free)

// Scratch (static device globals — no allocation)
__device__ __align__(16) __half g_h0h[NN * DD];   // h0 in fp16 (gather table)
__device__ int g_cur[NN];                         // slot cursor == degree
__device__ __align__(16) int g_csr[NN * CAP];
// [0]=cr_init, [1]=scale_m, [2]=scale_fin, [3]=cr0
__device__ float g_scalars[4];

// ---- tf32 mma helpers ----
__device__ __forceinline__ float to_tf32(float f) {
    unsigned u;
    asm("cvt.rna.tf32.f32 %0, %1;" : "=r"(u) : "f"(f));
    return __uint_as_float(u);
}

__device__ __forceinline__ void mma_tf32(float* d, const unsigned* a,
                                         const unsigned* b) {
    asm volatile(
        "mma.sync.aligned.m16n8k8.row.col.f32.tf32.tf32.f32 "
        "{%0,%1,%2,%3}, {%4,%5,%6,%7}, {%8,%9}, {%0,%1,%2,%3};\n"
        : "+f"(d[0]), "+f"(d[1]), "+f"(d[2]), "+f"(d[3])
        : "r"(a[0]), "r"(a[1]), "r"(a[2]), "r"(a[3]),
          "r"(b[0]), "r"(b[1]));
}

__device__ __forceinline__ float warp_reduce_add(float v) {
#pragma unroll
    for (int o = 16; o; o >>= 1) v += __shfl_xor_sync(0xffffffffu, v, o);
    return v;
}

// 4-lane quad sum (lanes differing in bits 0..1)
__device__ __forceinline__ float quad_reduce_add(float v) {
    v += __shfl_xor_sync(0xffffffffu, v, 1);
    v += __shfl_xor_sync(0xffffffffu, v, 2);
    return v;
}

__device__ __forceinline__ float compute_scale(float cr_cur, float cr_ref) {
    float ratio = cr_ref / (cr_cur + EPSF);
    bool cond = (!isnan(cr_cur)) && (!isnan(cr_ref)) &&
                (fabsf(cr_cur) > EPSF) && (fabsf(cr_ref) > EPSF) &&
                (ratio > EPSF);
    float s = cond ? sqrtf(fabsf(ratio)) : 1.0f;
    if (!isfinite(s)) s = 1.0f;  // 'ok' guard
    return s;
}

// cr over 4 rows at pointer with row stride 64 floats (smem or global)
__device__ __forceinline__ float cr_rows(const float* hs, int lane) {
    float sgn = (lane == 31) ? -1.0f : 1.0f;
    float a0 = hs[0 * DD + lane], a1 = hs[0 * DD + lane + 32];
    float b0 = hs[1 * DD + lane], b1 = hs[1 * DD + lane + 32];
    float c0 = hs[2 * DD + lane], c1 = hs[2 * DD + lane + 32];
    float d0 = hs[3 * DD + lane], d1 = hs[3 * DD + lane + 32];
    float hac = warp_reduce_add(a0 * c0 + sgn * a1 * c1);
    float hbd = warp_reduce_add(b0 * d0 + sgn * b1 * d1);
    float had = warp_reduce_add(a0 * d0 + sgn * a1 * d1);
    float hbc = warp_reduce_add(b0 * c0 + sgn * b1 * c1);
    return (hac * hbd) / (had * hbc + EPSF);
}

// --------------------------------------------------------------------------
// Single-pass fixed-capacity CSR fill; 4 edges per thread via int4 loads.
// --------------------------------------------------------------------------
__global__ void fill_kernel(const int4* __restrict__ src4,
                            const int4* __restrict__ dst4) {
    int t = blockIdx.x * blockDim.x + threadIdx.x;
    if (t >= EE / 4) return;
    int4 s = __ldg(&src4[t]);
    int4 d = __ldg(&dst4[t]);
#pragma unroll
    for (int j = 0; j < 4; j++) {
        int dd = (&d.x)[j];
        int ss = (&s.x)[j];
        int p = atomicAdd(&g_cur[dd], 1);
        if (p < CAP) g_csr[dd * CAP + p] = ss;
    }
}

// --------------------------------------------------------------------------
// gemm0 (tf32 MMA): g_h0h = half(normalize(X @ W0 + b0)).
// 128 rows x 64 cols per block, 256 threads (8 warps), warp-private
// 16-row strips. Block 0 also stores cr_init (from fp32 global x) and cr0.
// --------------------------------------------------------------------------
__global__ void __launch_bounds__(256, 3)
gemm0_kernel(const float* __restrict__ Xin, const float* __restrict__ W,
             const float* __restrict__ B) {
    extern __shared__ float smdyn[];
    float* ws = smdyn;                                   // [64][WS_STRIDE]
    float* xs = smdyn + 64 * WS_STRIDE;                  // [128][XS_STRIDE]
    float* crbuf = smdyn + 64 * WS_STRIDE + 128 * XS_STRIDE;  // [4][64]

    int tid = threadIdx.x;
    int rbase = blockIdx.x * 128;

    // W tile (tf32)
#pragma unroll
    for (int i = 0; i < 4; i++) {
        int e4 = tid + i * 256;
        float4 w4 = ((const float4*)W)[e4];
        int k = (e4 * 4) >> 6, n = (e4 * 4) & 63;
        *(float4*)&ws[k * WS_STRIDE + n] =
            make_float4(to_tf32(w4.x), to_tf32(w4.y),
                        to_tf32(w4.z), to_tf32(w4.w));
    }
    // X rows (tf32)
#pragma unroll
    for (int i = 0; i < 8; i++) {
        int idx = tid + i * 256;
        int rr = idx >> 4, kk = (idx & 15) * 4;
        int gr = rbase + rr;
        float4 v = make_float4(0.f, 0.f, 0.f, 0.f);
        if (gr < NN) v = *(const float4*)&Xin[gr * DD + kk];
        *(float4*)&xs[rr * XS_STRIDE + kk] =
            make_float4(to_tf32(v.x), to_tf32(v.y),
                        to_tf32(v.z), to_tf32(v.w));
    }
    __syncthreads();

    int warp = tid >> 5;
    int lane = tid & 31;
    int grp = lane >> 2;
    int tid4 = lane & 3;
    int mrow = warp * 16;

    float d[8][4];
#pragma unroll
    for (int nt = 0; nt < 8; nt++)
#pragma unroll
        for (int j = 0; j < 4; j++) d[nt][j] = 0.f;
#pragma unroll
    for (int ks = 0; ks < 8; ks++) {
        unsigned a[4];
        const float* xr0 = xs + (mrow + grp) * XS_STRIDE + ks * 8 + tid4;
        const float* xr1 = xr0 + 8 * XS_STRIDE;
        a[0] = __float_as_uint(xr0[0]);
        a[1] = __float_as_uint(xr1[0]);
        a[2] = __float_as_uint(xr0[4]);
        a[3] = __float_as_uint(xr1[4]);
#pragma unroll
        for (int nt = 0; nt < 8; nt++) {
            unsigned b[2];
            const float* wr = ws + (ks * 8 + tid4) * WS_STRIDE + nt * 8 + grp;
            b[0] = __float_as_uint(wr[0]);
            b[1] = __float_as_uint(wr[4 * WS_STRIDE]);
            mma_tf32(d[nt], a, b);
        }
    }

    // epilogue: normalize(acc + b), store fp16
    {
        int gr0 = rbase + mrow + grp;
        int gr1 = gr0 + 8;
        float ss0 = 0.f, ss1 = 0.f;
#pragma unroll
        for (int nt = 0; nt < 8; nt++) {
            float bb0 = __ldg(&B[nt * 8 + tid4 * 2 + 0]);
            float bb1 = __ldg(&B[nt * 8 + tid4 * 2 + 1]);
            d[nt][0] += bb0; d[nt][1] += bb1;
            d[nt][2] += bb0; d[nt][3] += bb1;
            ss0 += d[nt][0] * d[nt][0] + d[nt][1] * d[nt][1];
            ss1 += d[nt][2] * d[nt][2] + d[nt][3] * d[nt][3];
        }
        ss0 = quad_reduce_add(ss0);
        ss1 = quad_reduce_add(ss1);
        float inv0 = 1.f / (sqrtf(ss0) + EPSF);
        float inv1 = 1.f / (sqrtf(ss1) + EPSF);
#pragma unroll
        for (int nt = 0; nt < 8; nt++) {
            float v0 = d[nt][0] * inv0, v1 = d[nt][1] * inv0;
            float v2 = d[nt][2] * inv1, v3 = d[nt][3] * inv1;
            if (gr0 < NN) {
                __half2 h = __floats2half2_rn(v0, v1);
                *(__half2*)&g_h0h[gr0 * DD + nt * 8 + tid4 * 2] = h;
            }
            if (gr1 < NN) {
                __half2 h = __floats2half2_rn(v2, v3);
                *(__half2*)&g_h0h[gr1 * DD + nt * 8 + tid4 * 2] = h;
            }
            if (blockIdx.x == 0 && warp == 0 && grp < 4) {
                crbuf[grp * 64 + nt * 8 + tid4 * 2 + 0] = v0;
                crbuf[grp * 64 + nt * 8 + tid4 * 2 + 1] = v1;
            }
        }
    }

    if (blockIdx.x == 0) {
        __syncthreads();
        if (tid < 32) {
            float cr = cr_rows(crbuf, tid);
            if (tid == 0) g_scalars[3] = cr;       // cr0 (of h0)
        } else if (tid < 64) {
            float cr = cr_rows(Xin, tid - 32);     // fp32 global x rows 0..3
            if (tid == 32) g_scalars[0] = cr;      // cr_init
        }
    }
}

// --------------------------------------------------------------------------
// Fused gemm12 with tf32 tensor-core MMA + pipelined gather.
// 128 rows x 64 cols per block, 256 threads (8 warps), warp-private strips.
// --------------------------------------------------------------------------
__global__ void __launch_bounds__(256, 3)
gemm12_kernel(const float* __restrict__ Wm, const float* __restrict__ bm,
              const float* __restrict__ W1, const float* __restrict__ b1,
              float* __restrict__ Yout) {
    extern __shared__ float smdyn[];
    float* wsm = smdyn;                       // [64][WS_STRIDE]
    float* ws1 = smdyn + 64 * WS_STRIDE;      // [64][WS_STRIDE]
    float* xs  = smdyn + 128 * WS_STRIDE;     // [128][XS_STRIDE]

    int tid = threadIdx.x;
    int rbase = blockIdx.x * 128;

    // W tiles (tf32-rounded at store)
#pragma unroll
    for (int i = 0; i < 4; i++) {
        int e4 = tid + i * 256;
        float4 wm4 = ((const float4*)Wm)[e4];
        float4 w14 = ((const float4*)W1)[e4];
        int k = (e4 * 4) >> 6, n = (e4 * 4) & 63;
        *(float4*)&wsm[k * WS_STRIDE + n] =
            make_float4(to_tf32(wm4.x), to_tf32(wm4.y),
                        to_tf32(wm4.z), to_tf32(wm4.w));
        *(float4*)&ws1[k * WS_STRIDE + n] =
            make_float4(to_tf32(w14.x), to_tf32(w14.y),
                        to_tf32(w14.z), to_tf32(w14.w));
    }

    // Fused fp16 gather with index prefetch: 32 groups of 8 threads; group
    // handles row it*32+grp; thread q covers 16B (8 halfs) of the 128B row.
    {
        int grp = tid >> 3;
        int q = tid & 7;
#pragma unroll
        for (int it = 0; it < 4; it++) {
            int rr = it * 32 + grp;
            int n = rbase + rr;
            float a[8];
#pragma unroll
            for (int j = 0; j < 8; j++) a[j] = 0.f;
            if (n < NN) {
                int dg = min(g_cur[n], CAP);
                const int4* lst4 = (const int4*)&g_csr[n * CAP];
                const __half* tb = g_h0h;
                int nq = dg >> 2;
                if (nq > 0) {
                    int4 s4 = __ldg(&lst4[0]);
                    for (int qi = 0; qi < nq; qi++) {
                        int4 nxt = s4;
                        if (qi + 1 < nq) nxt = __ldg(&lst4[qi + 1]);
                        uint4 r0 = *(const uint4*)&tb[s4.x * DD + q * 8];
                        uint4 r1 = *(const uint4*)&tb[s4.y * DD + q * 8];
                        uint4 r2 = *(const uint4*)&tb[s4.z * DD + q * 8];
                        uint4 r3 = *(const uint4*)&tb[s4.w * DD + q * 8];
#pragma unroll
                        for (int c = 0; c < 4; c++) {
                            unsigned u0 = (&r0.x)[c], u1 = (&r1.x)[c];
                            unsigned u2 = (&r2.x)[c], u3 = (&r3.x)[c];
                            float2 f0 = __half22float2(*(__half2*)&u0);
                            float2 f1 = __half22float2(*(__half2*)&u1);
                            float2 f2 = __half22float2(*(__half2*)&u2);
                            float2 f3 = __half22float2(*(__half2*)&u3);
                            a[c * 2 + 0] += (f0.x + f1.x) + (f2.x + f3.x);
                            a[c * 2 + 1] += (f0.y + f1.y) + (f2.y + f3.y);
                        }
                        s4 = nxt;
                    }
                }
                for (int i = nq * 4; i < dg; i++) {
                    int s0 = g_csr[n * CAP + i];
                    uint4 r0 = *(const uint4*)&tb[s0 * DD + q * 8];
#pragma unroll
                    for (int c = 0; c < 4; c++) {
                        unsigned u0 = (&r0.x)[c];
                        float2 f0 = __half22float2(*(__half2*)&u0);
                        a[c * 2 + 0] += f0.x;
                        a[c * 2 + 1] += f0.y;
                    }
                }
            }
#pragma unroll
            for (int j = 0; j < 8; j++) a[j] = to_tf32(a[j]);
            *(float4*)&xs[rr * XS_STRIDE + q * 8 + 0] =
                make_float4(a[0], a[1], a[2], a[3]);
            *(float4*)&xs[rr * XS_STRIDE + q * 8 + 4] =
                make_float4(a[4], a[5], a[6], a[7]);
        }
    }
    __syncthreads();   // only barrier: rows become warp-private from here

    int warp = tid >> 5;
    int lane = tid & 31;
    int grp = lane >> 2;
    int tid4 = lane & 3;
    int mrow = warp * 16;

    float d[8][4];

    // ---- pass 1: agg @ Wm ----
#pragma unroll
    for (int nt = 0; nt < 8; nt++)
#pragma unroll
        for (int j = 0; j < 4; j++) d[nt][j] = 0.f;
#pragma unroll
    for (int ks = 0; ks < 8; ks++) {
        unsigned a[4];
        const float* xr0 = xs + (mrow + grp) * XS_STRIDE + ks * 8 + tid4;
        const float* xr1 = xr0 + 8 * XS_STRIDE;
        a[0] = __float_as_uint(xr0[0]);
        a[1] = __float_as_uint(xr1[0]);
        a[2] = __float_as_uint(xr0[4]);
        a[3] = __float_as_uint(xr1[4]);
#pragma unroll
        for (int nt = 0; nt < 8; nt++) {
            unsigned b[2];
            const float* wr = wsm + (ks * 8 + tid4) * WS_STRIDE + nt * 8 + grp;
            b[0] = __float_as_uint(wr[0]);
            b[1] = __float_as_uint(wr[4 * WS_STRIDE]);
            mma_tf32(d[nt], a, b);
        }
    }

    // pass-1 epilogue: hm = normalize(acc/deg + bm) -> xs (tf32)
    {
        int gr0 = rbase + mrow + grp;
        int gr1 = gr0 + 8;
        float c0 = (gr0 < NN) ? (float)min(g_cur[gr0], CAP) : 1.f;
        float c1 = (gr1 < NN) ? (float)min(g_cur[gr1], CAP) : 1.f;
        float rs0 = 1.f / fmaxf(c0, 1.f);
        float rs1 = 1.f / fmaxf(c1, 1.f);
        float ss0 = 0.f, ss1 = 0.f;
#pragma unroll
        for (int nt = 0; nt < 8; nt++) {
            float bb0 = __ldg(&bm[nt * 8 + tid4 * 2 + 0]);
            float bb1 = __ldg(&bm[nt * 8 + tid4 * 2 + 1]);
            d[nt][0] = fmaf(d[nt][0], rs0, bb0);
            d[nt][1] = fmaf(d[nt][1], rs0, bb1);
            d[nt][2] = fmaf(d[nt][2], rs1, bb0);
            d[nt][3] = fmaf(d[nt][3], rs1, bb1);
            ss0 += d[nt][0] * d[nt][0] + d[nt][1] * d[nt][1];
            ss1 += d[nt][2] * d[nt][2] + d[nt][3] * d[nt][3];
        }
        ss0 = quad_reduce_add(ss0);
        ss1 = quad_reduce_add(ss1);
        float inv0 = 1.f / (sqrtf(ss0) + EPSF);
        float inv1 = 1.f / (sqrtf(ss1) + EPSF);
#pragma unroll
        for (int nt = 0; nt < 8; nt++) {
            float2 lo = make_float2(to_tf32(d[nt][0] * inv0),
                                    to_tf32(d[nt][1] * inv0));
            float2 hi = make_float2(to_tf32(d[nt][2] * inv1),
                                    to_tf32(d[nt][3] * inv1));
            *(float2*)&xs[(mrow + grp) * XS_STRIDE + nt * 8 + tid4 * 2] = lo;
            *(float2*)&xs[(mrow + grp + 8) * XS_STRIDE + nt * 8 + tid4 * 2] = hi;
        }
    }
    // no barrier: each warp reads back only its own rows

    // ---- pass 2: hm @ W1 ----
#pragma unroll
    for (int nt = 0; nt < 8; nt++)
#pragma unroll
        for (int j = 0; j < 4; j++) d[nt][j] = 0.f;
#pragma unroll
    for (int ks = 0; ks < 8; ks++) {
        unsigned a[4];
        const float* xr0 = xs + (mrow + grp) * XS_STRIDE + ks * 8 + tid4;
        const float* xr1 = xr0 + 8 * XS_STRIDE;
        a[0] = __float_as_uint(xr0[0]);
        a[1] = __float_as_uint(xr1[0]);
        a[2] = __float_as_uint(xr0[4]);
        a[3] = __float_as_uint(xr1[4]);
#pragma unroll
        for (int nt = 0; nt < 8; nt++) {
            unsigned b[2];
            const float* wr = ws1 + (ks * 8 + tid4) * WS_STRIDE + nt * 8 + grp;
            b[0] = __float_as_uint(wr[0]);
            b[1] = __float_as_uint(wr[4 * WS_STRIDE]);
            mma_tf32(d[nt], a, b);
        }
    }

    // pass-2 epilogue: out = sf * relu(normalize(sm*acc + b1))
    {
        float sm = g_scalars[1];
        float sf = g_scalars[2];
        int gr0 = rbase + mrow + grp;
        int gr1 = gr0 + 8;
        float ss0 = 0.f, ss1 = 0.f;
#pragma unroll
        for (int nt = 0; nt < 8; nt++) {
            float bb0 = __ldg(&b1[nt * 8 + tid4 * 2 + 0]);
            float bb1 = __ldg(&b1[nt * 8 + tid4 * 2 + 1]);
            d[nt][0] = fmaf(sm, d[nt][0], bb0);
            d[nt][1] = fmaf(sm, d[nt][1], bb1);
            d[nt][2] = fmaf(sm, d[nt][2], bb0);
            d[nt][3] = fmaf(sm, d[nt][3], bb1);
            ss0 += d[nt][0] * d[nt][0] + d[nt][1] * d[nt][1];
            ss1 += d[nt][2] * d[nt][2] + d[nt][3] * d[nt][3];
        }
        ss0 = quad_reduce_add(ss0);
        ss1 = quad_reduce_add(ss1);
        float inv0 = sf / (sqrtf(ss0) + EPSF);
        float inv1 = sf / (sqrtf(ss1) + EPSF);
#pragma unroll
        for (int nt = 0; nt < 8; nt++) {
            if (gr0 < NN) {
                float2 lo = make_float2(fmaxf(d[nt][0], 0.f) * inv0,
                                        fmaxf(d[nt][1], 0.f) * inv0);
                *(float2*)&Yout[gr0 * DD + nt * 8 + tid4 * 2] = lo;
            }
            if (gr1 < NN) {
                float2 hi = make_float2(fmaxf(d[nt][2], 0.f) * inv1,
                                        fmaxf(d[nt][3], 0.f) * inv1);
                *(float2*)&Yout[gr1 * DD + nt * 8 + tid4 * 2] = hi;
            }
        }
    }
}

// --------------------------------------------------------------------------
// Merged small kernel: rows 0..3 of both remaining layers -> scale_m and
// scale_fin (fp32 path).
// --------------------------------------------------------------------------
__global__ void small4_kernel(const float* __restrict__ Wm,
                              const float* __restrict__ bm,
                              const float* __restrict__ W1,
                              const float* __restrict__ b1) {
    __shared__ float ins[4][DD];
    __shared__ float hs[4][DD];
    __shared__ float red[8];
    __shared__ float s_scale;
    int tid = threadIdx.x;
    int r = tid >> 6, c = tid & 63;

    // phase A: message rows 0..3 -> hm rows, scale_m
    {
        int dg = min(g_cur[r], CAP);
        const int* lst = &g_csr[r * CAP];
        float s = 0.f;
        for (int i = 0; i < dg; i++)
            s += __half2float(g_h0h[lst[i] * DD + c]);
        ins[r][c] = s / fmaxf((float)dg, 1.f);
    }
    __syncthreads();
    float acc = 0.f;
#pragma unroll
    for (int k = 0; k < 64; k++) acc = fmaf(ins[r][k], Wm[k * DD + c], acc);
    acc += bm[c];
    float ss = acc * acc;
#pragma unroll
    for (int o = 16; o; o >>= 1) ss += __shfl_xor_sync(0xffffffffu, ss, o);
    if ((tid & 31) == 0) red[tid >> 5] = ss;
    __syncthreads();
    float tot = red[r * 2] + red[r * 2 + 1];
    float y = acc / (sqrtf(tot) + EPSF);
    hs[r][c] = y;
    __syncthreads();
    if (tid < 32) {
        float cr_cur = cr_rows(&hs[0][0], tid);
        if (tid == 0) {
            float sc = compute_scale(cr_cur, g_scalars[3]);
            g_scalars[1] = sc;
            s_scale = sc;
        }
    }
    __syncthreads();

    // phase B: final rows 0..3 -> scale_fin
    float accB = 0.f;
#pragma unroll
    for (int k = 0; k < 64; k++) accB = fmaf(hs[r][k], W1[k * DD + c], accB);
    accB = fmaf(s_scale, accB, b1[c]);
    float ssB = accB * accB;
#pragma unroll
    for (int o = 16; o; o >>= 1) ssB += __shfl_xor_sync(0xffffffffu, ssB, o);
    if ((tid & 31) == 0) red[tid >> 5] = ssB;
    __syncthreads();
    float totB = red[r * 2] + red[r * 2 + 1];
    float yB = fmaxf(accB / (sqrtf(totB) + EPSF), 0.f);
    ins[r][c] = yB;   // reuse ins
    __syncthreads();
    if (tid < 32) {
        float cr2 = cr_rows(&ins[0][0], tid);
        if (tid == 0)
            g_scalars[2] = compute_scale(cr2, g_scalars[0]);
    }
}

// --------------------------------------------------------------------------
extern "C" void kernel_launch(void* const* d_in, const int* in_sizes, int n_in,
                              void* d_out, int out_size) {
    const float* x  = (const float*)d_in[0];
    const int*  ei  = (const int*)d_in[1];
    const float* W0 = (const float*)d_in[2];
    const float* b0 = (const float*)d_in[3];
    const float* Wm = (const float*)d_in[4];
    const float* bm = (const float*)d_in[5];
    const float* W1 = (const float*)d_in[6];
    const float* b1 = (const float*)d_in[7];
    float* out = (float*)d_out;
    const int4* src4 = (const int4*)ei;
    const int4* dst4 = (const int4*)(ei + EE);

    const int gblocks = (NN + 127) / 128;   // 782
    const int eblocks = (EE / 4 + 255) / 256;
    const int SMEM0 = (64 * WS_STRIDE + 128 * XS_STRIDE + 256) * 4;  // 54272
    const int SMEM12 = (128 * WS_STRIDE + 128 * XS_STRIDE) * 4;      // 71680

    // one-time host objects (host-side only; identical work every call)
    static cudaStream_t s2 = nullptr;
    static cudaEvent_t evF, evA, evFill, evB;
    static void* curp = nullptr;
    if (!s2) {
        cudaStreamCreateWithFlags(&s2, cudaStreamNonBlocking);
        cudaEventCreateWithFlags(&evF, cudaEventDisableTiming);
        cudaEventCreateWithFlags(&evA, cudaEventDisableTiming);
        cudaEventCreateWithFlags(&evFill, cudaEventDisableTiming);
        cudaEventCreateWithFlags(&evB, cudaEventDisableTiming);
        cudaGetSymbolAddress(&curp, g_cur);
        cudaFuncSetAttribute(gemm0_kernel,
                             cudaFuncAttributeMaxDynamicSharedMemorySize,
                             SMEM0);
        cudaFuncSetAttribute(gemm12_kernel,
                             cudaFuncAttributeMaxDynamicSharedMemorySize,
                             SMEM12);
    }

    cudaStream_t s0 = 0;  // capture stream

    // fork: gemm0 on s2, concurrent with CSR build on s0
    cudaEventRecord(evF, s0);
    cudaStreamWaitEvent(s2, evF, 0);
    gemm0_kernel<<<gblocks, 256, SMEM0, s2>>>(x, W0, b0);
    cudaEventRecord(evA, s2);

    // CSR build on s0
    cudaMemsetAsync(curp, 0, NN * sizeof(int), s0);
    fill_kernel<<<eblocks, 256, 0, s0>>>(src4, dst4);
    cudaEventRecord(evFill, s0);

    // small4 on s2 (after gemm0 [stream order] + fill)
    cudaStreamWaitEvent(s2, evFill, 0);
    small4_kernel<<<1, 256, 0, s2>>>(Wm, bm, W1, b1);
    cudaEventRecord(evB, s2);

    // fused tensor-core gemm12 on s0 (after fill + gemm0 + small4)
    cudaStreamWaitEvent(s0, evA, 0);
    cudaStreamWaitEvent(s0, evB, 0);
    gemm12_kernel<<<gblocks, 256, SMEM12, s0>>>(Wm, bm, W1, b1, out);
}

// round 11
// speedup vs baseline: 1.7298x; 1.0010x over previous
#include <cuda_runtime.h>
#include <cuda_fp16.h>
#include <cstdint>
#include <math.h>

#define NN 100000
#define DD 64
#define EE 1600000
#define EPSF 1e-8f
#define CAP 64   // fixed CSR capacity per node (deg ~ Poisson(16); P(>64)~1e-19)

#define WS_STRIDE 72   // W smem row stride in floats (conflict-free B frags)
#define XS_STRIDE 68   // gemm0 X smem row stride in floats
#define XSH_STRIDE 72  // gemm12 X smem row stride in halfs (144B, 16B-aligned)

// Scratch (static device globals — no allocation)
__device__ __align__(16) __half g_h0h[NN * DD];   // h0 in fp16 (gather table)
__device__ int g_cur[NN];                         // slot cursor == degree
__device__ __align__(16) int g_csr[NN * CAP];
// [0]=cr_init, [1]=scale_m, [2]=scale_fin, [3]=cr0
__device__ float g_scalars[4];

// ---- tf32 mma helpers ----
__device__ __forceinline__ float to_tf32(float f) {
    unsigned u;
    asm("cvt.rna.tf32.f32 %0, %1;" : "=r"(u) : "f"(f));
    return __uint_as_float(u);
}

__device__ __forceinline__ void mma_tf32(float* d, const unsigned* a,
                                         const unsigned* b) {
    asm volatile(
        "mma.sync.aligned.m16n8k8.row.col.f32.tf32.tf32.f32 "
        "{%0,%1,%2,%3}, {%4,%5,%6,%7}, {%8,%9}, {%0,%1,%2,%3};\n"
        : "+f"(d[0]), "+f"(d[1]), "+f"(d[2]), "+f"(d[3])
        : "r"(a[0]), "r"(a[1]), "r"(a[2]), "r"(a[3]),
          "r"(b[0]), "r"(b[1]));
}

__device__ __forceinline__ float warp_reduce_add(float v) {
#pragma unroll
    for (int o = 16; o; o >>= 1) v += __shfl_xor_sync(0xffffffffu, v, o);
    return v;
}

// 4-lane quad sum (lanes differing in bits 0..1)
__device__ __forceinline__ float quad_reduce_add(float v) {
    v += __shfl_xor_sync(0xffffffffu, v, 1);
    v += __shfl_xor_sync(0xffffffffu, v, 2);
    return v;
}

__device__ __forceinline__ float compute_scale(float cr_cur, float cr_ref) {
    float ratio = cr_ref / (cr_cur + EPSF);
    bool cond = (!isnan(cr_cur)) && (!isnan(cr_ref)) &&
                (fabsf(cr_cur) > EPSF) && (fabsf(cr_ref) > EPSF) &&
                (ratio > EPSF);
    float s = cond ? sqrtf(fabsf(ratio)) : 1.0f;
    if (!isfinite(s)) s = 1.0f;  // 'ok' guard
    return s;
}

// cr over 4 rows at pointer with row stride 64 floats (smem or global)
__device__ __forceinline__ float cr_rows(const float* hs, int lane) {
    float sgn = (lane == 31) ? -1.0f : 1.0f;
    float a0 = hs[0 * DD + lane], a1 = hs[0 * DD + lane + 32];
    float b0 = hs[1 * DD + lane], b1 = hs[1 * DD + lane + 32];
    float c0 = hs[2 * DD + lane], c1 = hs[2 * DD + lane + 32];
    float d0 = hs[3 * DD + lane], d1 = hs[3 * DD + lane + 32];
    float hac = warp_reduce_add(a0 * c0 + sgn * a1 * c1);
    float hbd = warp_reduce_add(b0 * d0 + sgn * b1 * d1);
    float had = warp_reduce_add(a0 * d0 + sgn * a1 * d1);
    float hbc = warp_reduce_add(b0 * c0 + sgn * b1 * c1);
    return (hac * hbd) / (had * hbc + EPSF);
}

// --------------------------------------------------------------------------
// Single-pass fixed-capacity CSR fill; 4 edges per thread via int4 loads.
// --------------------------------------------------------------------------
__global__ void fill_kernel(const int4* __restrict__ src4,
                            const int4* __restrict__ dst4) {
    int t = blockIdx.x * blockDim.x + threadIdx.x;
    if (t >= EE / 4) return;
    int4 s = __ldg(&src4[t]);
    int4 d = __ldg(&dst4[t]);
#pragma unroll
    for (int j = 0; j < 4; j++) {
        int dd = (&d.x)[j];
        int ss = (&s.x)[j];
        int p = atomicAdd(&g_cur[dd], 1);
        if (p < CAP) g_csr[dd * CAP + p] = ss;
    }
}

// --------------------------------------------------------------------------
// gemm0 (tf32 MMA): g_h0h = half(normalize(X @ W0 + b0)).
// 128 rows x 64 cols per block, 256 threads (8 warps), warp-private
// 16-row strips. Block 0 also stores cr_init (from fp32 global x) and cr0.
// --------------------------------------------------------------------------
__global__ void __launch_bounds__(256, 3)
gemm0_kernel(const float* __restrict__ Xin, const float* __restrict__ W,
             const float* __restrict__ B) {
    extern __shared__ float smdyn[];
    float* ws = smdyn;                                   // [64][WS_STRIDE]
    float* xs = smdyn + 64 * WS_STRIDE;                  // [128][XS_STRIDE]
    float* crbuf = smdyn + 64 * WS_STRIDE + 128 * XS_STRIDE;  // [4][64]

    int tid = threadIdx.x;
    int rbase = blockIdx.x * 128;

    // W tile (tf32)
#pragma unroll
    for (int i = 0; i < 4; i++) {
        int e4 = tid + i * 256;
        float4 w4 = ((const float4*)W)[e4];
        int k = (e4 * 4) >> 6, n = (e4 * 4) & 63;
        *(float4*)&ws[k * WS_STRIDE + n] =
            make_float4(to_tf32(w4.x), to_tf32(w4.y),
                        to_tf32(w4.z), to_tf32(w4.w));
    }
    // X rows (tf32)
#pragma unroll
    for (int i = 0; i < 8; i++) {
        int idx = tid + i * 256;
        int rr = idx >> 4, kk = (idx & 15) * 4;
        int gr = rbase + rr;
        float4 v = make_float4(0.f, 0.f, 0.f, 0.f);
        if (gr < NN) v = *(const float4*)&Xin[gr * DD + kk];
        *(float4*)&xs[rr * XS_STRIDE + kk] =
            make_float4(to_tf32(v.x), to_tf32(v.y),
                        to_tf32(v.z), to_tf32(v.w));
    }
    __syncthreads();

    int warp = tid >> 5;
    int lane = tid & 31;
    int grp = lane >> 2;
    int tid4 = lane & 3;
    int mrow = warp * 16;

    float d[8][4];
#pragma unroll
    for (int nt = 0; nt < 8; nt++)
#pragma unroll
        for (int j = 0; j < 4; j++) d[nt][j] = 0.f;
#pragma unroll
    for (int ks = 0; ks < 8; ks++) {
        unsigned a[4];
        const float* xr0 = xs + (mrow + grp) * XS_STRIDE + ks * 8 + tid4;
        const float* xr1 = xr0 + 8 * XS_STRIDE;
        a[0] = __float_as_uint(xr0[0]);
        a[1] = __float_as_uint(xr1[0]);
        a[2] = __float_as_uint(xr0[4]);
        a[3] = __float_as_uint(xr1[4]);
#pragma unroll
        for (int nt = 0; nt < 8; nt++) {
            unsigned b[2];
            const float* wr = ws + (ks * 8 + tid4) * WS_STRIDE + nt * 8 + grp;
            b[0] = __float_as_uint(wr[0]);
            b[1] = __float_as_uint(wr[4 * WS_STRIDE]);
            mma_tf32(d[nt], a, b);
        }
    }

    // epilogue: normalize(acc + b), store fp16
    {
        int gr0 = rbase + mrow + grp;
        int gr1 = gr0 + 8;
        float ss0 = 0.f, ss1 = 0.f;
#pragma unroll
        for (int nt = 0; nt < 8; nt++) {
            float bb0 = __ldg(&B[nt * 8 + tid4 * 2 + 0]);
            float bb1 = __ldg(&B[nt * 8 + tid4 * 2 + 1]);
            d[nt][0] += bb0; d[nt][1] += bb1;
            d[nt][2] += bb0; d[nt][3] += bb1;
            ss0 += d[nt][0] * d[nt][0] + d[nt][1] * d[nt][1];
            ss1 += d[nt][2] * d[nt][2] + d[nt][3] * d[nt][3];
        }
        ss0 = quad_reduce_add(ss0);
        ss1 = quad_reduce_add(ss1);
        float inv0 = 1.f / (sqrtf(ss0) + EPSF);
        float inv1 = 1.f / (sqrtf(ss1) + EPSF);
#pragma unroll
        for (int nt = 0; nt < 8; nt++) {
            float v0 = d[nt][0] * inv0, v1 = d[nt][1] * inv0;
            float v2 = d[nt][2] * inv1, v3 = d[nt][3] * inv1;
            if (gr0 < NN) {
                __half2 h = __floats2half2_rn(v0, v1);
                *(__half2*)&g_h0h[gr0 * DD + nt * 8 + tid4 * 2] = h;
            }
            if (gr1 < NN) {
                __half2 h = __floats2half2_rn(v2, v3);
                *(__half2*)&g_h0h[gr1 * DD + nt * 8 + tid4 * 2] = h;
            }
            if (blockIdx.x == 0 && warp == 0 && grp < 4) {
                crbuf[grp * 64 + nt * 8 + tid4 * 2 + 0] = v0;
                crbuf[grp * 64 + nt * 8 + tid4 * 2 + 1] = v1;
            }
        }
    }

    if (blockIdx.x == 0) {
        __syncthreads();
        if (tid < 32) {
            float cr = cr_rows(crbuf, tid);
            if (tid == 0) g_scalars[3] = cr;       // cr0 (of h0)
        } else if (tid < 64) {
            float cr = cr_rows(Xin, tid - 32);     // fp32 global x rows 0..3
            if (tid == 32) g_scalars[0] = cr;      // cr_init
        }
    }
}

// --------------------------------------------------------------------------
// Fused gemm12, tf32 MMA, fp16 xs staging (fp16 mantissa == tf32 mantissa,
// so no extra precision loss vs tf32 staging). 128 rows x 64 cols per block,
// 256 threads, warp-private 16-row strips. 55.3KB smem + 64 regs ->
// 4 blocks/SM (was 3).
// --------------------------------------------------------------------------
__global__ void __launch_bounds__(256, 4)
gemm12_kernel(const float* __restrict__ Wm, const float* __restrict__ bm,
              const float* __restrict__ W1, const float* __restrict__ b1,
              float* __restrict__ Yout) {
    extern __shared__ float smdyn[];
    float* wsm = smdyn;                            // [64][WS_STRIDE] f32
    float* ws1 = smdyn + 64 * WS_STRIDE;           // [64][WS_STRIDE] f32
    __half* xs = (__half*)(smdyn + 128 * WS_STRIDE);  // [128][XSH_STRIDE] f16

    int tid = threadIdx.x;
    int rbase = blockIdx.x * 128;

    // W tiles (tf32-rounded at store)
#pragma unroll
    for (int i = 0; i < 4; i++) {
        int e4 = tid + i * 256;
        float4 wm4 = ((const float4*)Wm)[e4];
        float4 w14 = ((const float4*)W1)[e4];
        int k = (e4 * 4) >> 6, n = (e4 * 4) & 63;
        *(float4*)&wsm[k * WS_STRIDE + n] =
            make_float4(to_tf32(wm4.x), to_tf32(wm4.y),
                        to_tf32(wm4.z), to_tf32(wm4.w));
        *(float4*)&ws1[k * WS_STRIDE + n] =
            make_float4(to_tf32(w14.x), to_tf32(w14.y),
                        to_tf32(w14.z), to_tf32(w14.w));
    }

    // Fused fp16 gather with index prefetch: 32 groups of 8 threads; group
    // handles row it*32+grp; thread q covers 16B (8 halfs) of the 128B row.
    {
        int grp = tid >> 3;
        int q = tid & 7;
#pragma unroll
        for (int it = 0; it < 4; it++) {
            int rr = it * 32 + grp;
            int n = rbase + rr;
            float a[8];
#pragma unroll
            for (int j = 0; j < 8; j++) a[j] = 0.f;
            if (n < NN) {
                int dg = min(g_cur[n], CAP);
                const int4* lst4 = (const int4*)&g_csr[n * CAP];
                const __half* tb = g_h0h;
                int nq = dg >> 2;
                if (nq > 0) {
                    int4 s4 = __ldg(&lst4[0]);
                    for (int qi = 0; qi < nq; qi++) {
                        int4 nxt = s4;
                        if (qi + 1 < nq) nxt = __ldg(&lst4[qi + 1]);
                        uint4 r0 = *(const uint4*)&tb[s4.x * DD + q * 8];
                        uint4 r1 = *(const uint4*)&tb[s4.y * DD + q * 8];
                        uint4 r2 = *(const uint4*)&tb[s4.z * DD + q * 8];
                        uint4 r3 = *(const uint4*)&tb[s4.w * DD + q * 8];
#pragma unroll
                        for (int c = 0; c < 4; c++) {
                            unsigned u0 = (&r0.x)[c], u1 = (&r1.x)[c];
                            unsigned u2 = (&r2.x)[c], u3 = (&r3.x)[c];
                            float2 f0 = __half22float2(*(__half2*)&u0);
                            float2 f1 = __half22float2(*(__half2*)&u1);
                            float2 f2 = __half22float2(*(__half2*)&u2);
                            float2 f3 = __half22float2(*(__half2*)&u3);
                            a[c * 2 + 0] += (f0.x + f1.x) + (f2.x + f3.x);
                            a[c * 2 + 1] += (f0.y + f1.y) + (f2.y + f3.y);
                        }
                        s4 = nxt;
                    }
                }
                for (int i = nq * 4; i < dg; i++) {
                    int s0 = g_csr[n * CAP + i];
                    uint4 r0 = *(const uint4*)&tb[s0 * DD + q * 8];
#pragma unroll
                    for (int c = 0; c < 4; c++) {
                        unsigned u0 = (&r0.x)[c];
                        float2 f0 = __half22float2(*(__half2*)&u0);
                        a[c * 2 + 0] += f0.x;
                        a[c * 2 + 1] += f0.y;
                    }
                }
            }
            // store as fp16 (10-bit mantissa == tf32; values O(1..64))
            __half2 h01 = __floats2half2_rn(a[0], a[1]);
            __half2 h23 = __floats2half2_rn(a[2], a[3]);
            __half2 h45 = __floats2half2_rn(a[4], a[5]);
            __half2 h67 = __floats2half2_rn(a[6], a[7]);
            uint4 u;
            u.x = *(unsigned*)&h01; u.y = *(unsigned*)&h23;
            u.z = *(unsigned*)&h45; u.w = *(unsigned*)&h67;
            *(uint4*)&xs[rr * XSH_STRIDE + q * 8] = u;
        }
    }
    __syncthreads();   // only barrier: rows become warp-private from here

    int warp = tid >> 5;
    int lane = tid & 31;
    int grp = lane >> 2;
    int tid4 = lane & 3;
    int mrow = warp * 16;

    float d[8][4];

    // ---- pass 1: agg @ Wm ----
#pragma unroll
    for (int nt = 0; nt < 8; nt++)
#pragma unroll
        for (int j = 0; j < 4; j++) d[nt][j] = 0.f;
#pragma unroll
    for (int ks = 0; ks < 8; ks++) {
        unsigned a[4];
        const __half* xr0 = xs + (mrow + grp) * XSH_STRIDE + ks * 8 + tid4;
        const __half* xr1 = xr0 + 8 * XSH_STRIDE;
        a[0] = __float_as_uint(__half2float(xr0[0]));
        a[1] = __float_as_uint(__half2float(xr1[0]));
        a[2] = __float_as_uint(__half2float(xr0[4]));
        a[3] = __float_as_uint(__half2float(xr1[4]));
#pragma unroll
        for (int nt = 0; nt < 8; nt++) {
            unsigned b[2];
            const float* wr = wsm + (ks * 8 + tid4) * WS_STRIDE + nt * 8 + grp;
            b[0] = __float_as_uint(wr[0]);
            b[1] = __float_as_uint(wr[4 * WS_STRIDE]);
            mma_tf32(d[nt], a, b);
        }
    }

    // pass-1 epilogue: hm = normalize(acc/deg + bm) -> xs (fp16)
    {
        int gr0 = rbase + mrow + grp;
        int gr1 = gr0 + 8;
        float c0 = (gr0 < NN) ? (float)min(g_cur[gr0], CAP) : 1.f;
        float c1 = (gr1 < NN) ? (float)min(g_cur[gr1], CAP) : 1.f;
        float rs0 = 1.f / fmaxf(c0, 1.f);
        float rs1 = 1.f / fmaxf(c1, 1.f);
        float ss0 = 0.f, ss1 = 0.f;
#pragma unroll
        for (int nt = 0; nt < 8; nt++) {
            float bb0 = __ldg(&bm[nt * 8 + tid4 * 2 + 0]);
            float bb1 = __ldg(&bm[nt * 8 + tid4 * 2 + 1]);
            d[nt][0] = fmaf(d[nt][0], rs0, bb0);
            d[nt][1] = fmaf(d[nt][1], rs0, bb1);
            d[nt][2] = fmaf(d[nt][2], rs1, bb0);
            d[nt][3] = fmaf(d[nt][3], rs1, bb1);
            ss0 += d[nt][0] * d[nt][0] + d[nt][1] * d[nt][1];
            ss1 += d[nt][2] * d[nt][2] + d[nt][3] * d[nt][3];
        }
        ss0 = quad_reduce_add(ss0);
        ss1 = quad_reduce_add(ss1);
        float inv0 = 1.f / (sqrtf(ss0) + EPSF);
        float inv1 = 1.f / (sqrtf(ss1) + EPSF);
#pragma unroll
        for (int nt = 0; nt < 8; nt++) {
            __half2 lo = __floats2half2_rn(d[nt][0] * inv0, d[nt][1] * inv0);
            __half2 hi = __floats2half2_rn(d[nt][2] * inv1, d[nt][3] * inv1);
            *(__half2*)&xs[(mrow + grp) * XSH_STRIDE + nt * 8 + tid4 * 2] = lo;
            *(__half2*)&xs[(mrow + grp + 8) * XSH_STRIDE + nt * 8 + tid4 * 2] = hi;
        }
    }
    // no barrier: each warp reads back only its own rows

    // ---- pass 2: hm @ W1 ----
#pragma unroll
    for (int nt = 0; nt < 8; nt++)
#pragma unroll
        for (int j = 0; j < 4; j++) d[nt][j] = 0.f;
#pragma unroll
    for (int ks = 0; ks < 8; ks++) {
        unsigned a[4];
        const __half* xr0 = xs + (mrow + grp) * XSH_STRIDE + ks * 8 + tid4;
        const __half* xr1 = xr0 + 8 * XSH_STRIDE;
        a[0] = __float_as_uint(__half2float(xr0[0]));
        a[1] = __float_as_uint(__half2float(xr1[0]));
        a[2] = __float_as_uint(__half2float(xr0[4]));
        a[3] = __float_as_uint(__half2float(xr1[4]));
#pragma unroll
        for (int nt = 0; nt < 8; nt++) {
            unsigned b[2];
            const float* wr = ws1 + (ks * 8 + tid4) * WS_STRIDE + nt * 8 + grp;
            b[0] = __float_as_uint(wr[0]);
            b[1] = __float_as_uint(wr[4 * WS_STRIDE]);
            mma_tf32(d[nt], a, b);
        }
    }

    // pass-2 epilogue: out = sf * relu(normalize(sm*acc + b1))
    {
        float sm = g_scalars[1];
        float sf = g_scalars[2];
        int gr0 = rbase + mrow + grp;
        int gr1 = gr0 + 8;
        float ss0 = 0.f, ss1 = 0.f;
#pragma unroll
        for (int nt = 0; nt < 8; nt++) {
            float bb0 = __ldg(&b1[nt * 8 + tid4 * 2 + 0]);
            float bb1 = __ldg(&b1[nt * 8 + tid4 * 2 + 1]);
            d[nt][0] = fmaf(sm, d[nt][0], bb0);
            d[nt][1] = fmaf(sm, d[nt][1], bb1);
            d[nt][2] = fmaf(sm, d[nt][2], bb0);
            d[nt][3] = fmaf(sm, d[nt][3], bb1);
            ss0 += d[nt][0] * d[nt][0] + d[nt][1] * d[nt][1];
            ss1 += d[nt][2] * d[nt][2] + d[nt][3] * d[nt][3];
        }
        ss0 = quad_reduce_add(ss0);
        ss1 = quad_reduce_add(ss1);
        float inv0 = sf / (sqrtf(ss0) + EPSF);
        float inv1 = sf / (sqrtf(ss1) + EPSF);
#pragma unroll
        for (int nt = 0; nt < 8; nt++) {
            if (gr0 < NN) {
                float2 lo = make_float2(fmaxf(d[nt][0], 0.f) * inv0,
                                        fmaxf(d[nt][1], 0.f) * inv0);
                *(float2*)&Yout[gr0 * DD + nt * 8 + tid4 * 2] = lo;
            }
            if (gr1 < NN) {
                float2 hi = make_float2(fmaxf(d[nt][2], 0.f) * inv1,
                                        fmaxf(d[nt][3], 0.f) * inv1);
                *(float2*)&Yout[gr1 * DD + nt * 8 + tid4 * 2] = hi;
            }
        }
    }
}

// --------------------------------------------------------------------------
// Merged small kernel: rows 0..3 of both remaining layers -> scale_m and
// scale_fin (fp32 path).
// --------------------------------------------------------------------------
__global__ void small4_kernel(const float* __restrict__ Wm,
                              const float* __restrict__ bm,
                              const float* __restrict__ W1,
                              const float* __restrict__ b1) {
    __shared__ float ins[4][DD];
    __shared__ float hs[4][DD];
    __shared__ float red[8];
    __shared__ float s_scale;
    int tid = threadIdx.x;
    int r = tid >> 6, c = tid & 63;

    // phase A: message rows 0..3 -> hm rows, scale_m
    {
        int dg = min(g_cur[r], CAP);
        const int* lst = &g_csr[r * CAP];
        float s = 0.f;
        for (int i = 0; i < dg; i++)
            s += __half2float(g_h0h[lst[i] * DD + c]);
        ins[r][c] = s / fmaxf((float)dg, 1.f);
    }
    __syncthreads();
    float acc = 0.f;
#pragma unroll
    for (int k = 0; k < 64; k++) acc = fmaf(ins[r][k], Wm[k * DD + c], acc);
    acc += bm[c];
    float ss = acc * acc;
#pragma unroll
    for (int o = 16; o; o >>= 1) ss += __shfl_xor_sync(0xffffffffu, ss, o);
    if ((tid & 31) == 0) red[tid >> 5] = ss;
    __syncthreads();
    float tot = red[r * 2] + red[r * 2 + 1];
    float y = acc / (sqrtf(tot) + EPSF);
    hs[r][c] = y;
    __syncthreads();
    if (tid < 32) {
        float cr_cur = cr_rows(&hs[0][0], tid);
        if (tid == 0) {
            float sc = compute_scale(cr_cur, g_scalars[3]);
            g_scalars[1] = sc;
            s_scale = sc;
        }
    }
    __syncthreads();

    // phase B: final rows 0..3 -> scale_fin
    float accB = 0.f;
#pragma unroll
    for (int k = 0; k < 64; k++) accB = fmaf(hs[r][k], W1[k * DD + c], accB);
    accB = fmaf(s_scale, accB, b1[c]);
    float ssB = accB * accB;
#pragma unroll
    for (int o = 16; o; o >>= 1) ssB += __shfl_xor_sync(0xffffffffu, ssB, o);
    if ((tid & 31) == 0) red[tid >> 5] = ssB;
    __syncthreads();
    float totB = red[r * 2] + red[r * 2 + 1];
    float yB = fmaxf(accB / (sqrtf(totB) + EPSF), 0.f);
    ins[r][c] = yB;   // reuse ins
    __syncthreads();
    if (tid < 32) {
        float cr2 = cr_rows(&ins[0][0], tid);
        if (tid == 0)
            g_scalars[2] = compute_scale(cr2, g_scalars[0]);
    }
}

// --------------------------------------------------------------------------
extern "C" void kernel_launch(void* const* d_in, const int* in_sizes, int n_in,
                              void* d_out, int out_size) {
    const float* x  = (const float*)d_in[0];
    const int*  ei  = (const int*)d_in[1];
    const float* W0 = (const float*)d_in[2];
    const float* b0 = (const float*)d_in[3];
    const float* Wm = (const float*)d_in[4];
    const float* bm = (const float*)d_in[5];
    const float* W1 = (const float*)d_in[6];
    const float* b1 = (const float*)d_in[7];
    float* out = (float*)d_out;
    const int4* src4 = (const int4*)ei;
    const int4* dst4 = (const int4*)(ei + EE);

    const int gblocks = (NN + 127) / 128;   // 782
    const int eblocks = (EE / 4 + 255) / 256;
    const int SMEM0 = (64 * WS_STRIDE + 128 * XS_STRIDE + 256) * 4;  // 54272
    const int SMEM12 = 128 * WS_STRIDE * 4 + 128 * XSH_STRIDE * 2;   // 55296

    // one-time host objects (host-side only; identical work every call)
    static cudaStream_t s2 = nullptr;
    static cudaEvent_t evF, evA, evFill, evB;
    static void* curp = nullptr;
    if (!s2) {
        cudaStreamCreateWithFlags(&s2, cudaStreamNonBlocking);
        cudaEventCreateWithFlags(&evF, cudaEventDisableTiming);
        cudaEventCreateWithFlags(&evA, cudaEventDisableTiming);
        cudaEventCreateWithFlags(&evFill, cudaEventDisableTiming);
        cudaEventCreateWithFlags(&evB, cudaEventDisableTiming);
        cudaGetSymbolAddress(&curp, g_cur);
        cudaFuncSetAttribute(gemm0_kernel,
                             cudaFuncAttributeMaxDynamicSharedMemorySize,
                             SMEM0);
        cudaFuncSetAttribute(gemm12_kernel,
                             cudaFuncAttributeMaxDynamicSharedMemorySize,
                             SMEM12);
    }

    cudaStream_t s0 = 0;  // capture stream

    // fork: gemm0 on s2, concurrent with CSR build on s0
    cudaEventRecord(evF, s0);
    cudaStreamWaitEvent(s2, evF, 0);
    gemm0_kernel<<<gblocks, 256, SMEM0, s2>>>(x, W0, b0);
    cudaEventRecord(evA, s2);

    // CSR build on s0
    cudaMemsetAsync(curp, 0, NN * sizeof(int), s0);
    fill_kernel<<<eblocks, 256, 0, s0>>>(src4, dst4);
    cudaEventRecord(evFill, s0);

    // small4 on s2 (after gemm0 [stream order] + fill)
    cudaStreamWaitEvent(s2, evFill, 0);
    small4_kernel<<<1, 256, 0, s2>>>(Wm, bm, W1, b1);
    cudaEventRecord(evB, s2);

    // fused tensor-core gemm12 on s0 (after fill + gemm0 + small4)
    cudaStreamWaitEvent(s0, evA, 0);
    cudaStreamWaitEvent(s0, evB, 0);
    gemm12_kernel<<<gblocks, 256, SMEM12, s0>>>(Wm, bm, W1, b1, out);
}